// round 2
// baseline (speedup 1.0000x reference)
#include <cuda_runtime.h>
#include <cuda_bf16.h>
#include <math.h>

// Problem constants (fixed for MixtureOfExperts_498216206779)
#define NB 4
#define NT 2048
#define ND 1024
#define NH 4096
#define NE 8
#define NTOK (NB*NT)          // 8192
#define CAP 1024              // max(4, ceil(1.0*8192/8))
#define MT (NE*CAP)           // 8192 total expert slots

// ---------------- scratch (device globals; no allocation allowed) ----------
__device__ float g_probs[NTOK*NE];
__device__ float g_lse2[NTOK];
__device__ int   g_expidx[NTOK];
__device__ float g_expprob[NTOK];
__device__ int   g_rank[NTOK];
__device__ int   g_sorted_tok[NTOK];
__device__ int   g_counts[NE];
__device__ int   g_tok_of_slot[MT];
__device__ float g_scale[NTOK];
__device__ float g_xbuf[(size_t)MT*ND];   // 32 MB
__device__ float g_hbuf[(size_t)MT*NH];   // 128 MB

// ---------------- router: logits, softmax, argmax, lse^2 -------------------
__global__ void router_kernel(const float* __restrict__ x,
                              const float* __restrict__ Wg)
{
    int warp = (blockIdx.x * blockDim.x + threadIdx.x) >> 5;
    int lane = threadIdx.x & 31;
    if (warp >= NTOK) return;
    const float* xr = x + (size_t)warp * ND;
    float acc[NE] = {0,0,0,0,0,0,0,0};
    for (int d = lane; d < ND; d += 32) {
        float xv = xr[d];
        const float* wr = Wg + d * NE;
        #pragma unroll
        for (int e = 0; e < NE; e++) acc[e] += xv * wr[e];
    }
    #pragma unroll
    for (int e = 0; e < NE; e++) {
        #pragma unroll
        for (int o = 16; o > 0; o >>= 1)
            acc[e] += __shfl_xor_sync(0xFFFFFFFFu, acc[e], o);
    }
    if (lane == 0) {
        float m = acc[0]; int am = 0;
        #pragma unroll
        for (int e = 1; e < NE; e++) if (acc[e] > m) { m = acc[e]; am = e; }
        float pe[NE]; float s = 0.f;
        #pragma unroll
        for (int e = 0; e < NE; e++) { pe[e] = expf(acc[e] - m); s += pe[e]; }
        float inv = 1.0f / s;
        #pragma unroll
        for (int e = 0; e < NE; e++) g_probs[warp*NE + e] = pe[e] * inv;
        float lse = logf(s) + m;
        g_lse2[warp]    = lse * lse;
        g_expidx[warp]  = am;
        g_expprob[warp] = pe[am] * inv;
    }
}

// ---------------- stable ranks via packed prefix scan (1 block) -------------
__global__ void rank_kernel()
{
    __shared__ unsigned long long h0[1024], h1[1024];
    __shared__ int stotal[NE], sstart[NE];
    int t = threadIdx.x;
    int base = t * 8;
    int e_arr[8];
    int cnt[NE] = {0,0,0,0,0,0,0,0};
    #pragma unroll
    for (int i = 0; i < 8; i++) { int e = g_expidx[base+i]; e_arr[i] = e; cnt[e]++; }
    unsigned long long p0 = 0, p1 = 0;
    #pragma unroll
    for (int e = 0; e < 4; e++) {
        p0 |= (unsigned long long)cnt[e]   << (16*e);
        p1 |= (unsigned long long)cnt[e+4] << (16*e);
    }
    h0[t] = p0; h1[t] = p1;
    __syncthreads();
    for (int off = 1; off < 1024; off <<= 1) {
        unsigned long long v0 = (t >= off) ? h0[t-off] : 0ULL;
        unsigned long long v1 = (t >= off) ? h1[t-off] : 0ULL;
        __syncthreads();
        h0[t] += v0; h1[t] += v1;
        __syncthreads();
    }
    unsigned long long inc0 = h0[t], inc1 = h1[t];
    if (t == 1023) {
        #pragma unroll
        for (int e = 0; e < 4; e++) {
            stotal[e]   = (int)((inc0 >> (16*e)) & 0xFFFF);
            stotal[e+4] = (int)((inc1 >> (16*e)) & 0xFFFF);
        }
    }
    // clear slot->token map (stale data from prior launch must not leak)
    for (int i = t; i < MT; i += 1024) g_tok_of_slot[i] = -1;
    __syncthreads();
    if (t == 0) { int s = 0; for (int e = 0; e < NE; e++) { sstart[e] = s; s += stotal[e]; } }
    if (t < NE) g_counts[t] = stotal[t];
    __syncthreads();
    int loc[NE];
    #pragma unroll
    for (int e = 0; e < 4; e++) {
        loc[e]   = (int)((inc0 >> (16*e)) & 0xFFFF) - cnt[e];
        loc[e+4] = (int)((inc1 >> (16*e)) & 0xFFFF) - cnt[e+4];
    }
    #pragma unroll
    for (int i = 0; i < 8; i++) {
        int n = base + i, e = e_arr[i];
        int r = loc[e]++;
        g_rank[n] = r;
        g_sorted_tok[sstart[e] + r] = n;
        if (r < CAP) g_tok_of_slot[e*CAP + r] = n;
    }
}

// ------------- gather tokens into expert buffers; zero dropped outs --------
__global__ void gather_kernel(const float* __restrict__ x, float* __restrict__ out)
{
    int n = blockIdx.x;
    int t = threadIdx.x;
    int e = g_expidx[n];
    int r = g_rank[n];
    if (t == 0) g_scale[n] = g_expprob[g_sorted_tok[n]];
    if (r < CAP) {
        float4* dst = (float4*)(g_xbuf + ((size_t)(e*CAP + r)) * ND);
        const float4* src = (const float4*)(x + (size_t)n * ND);
        dst[t] = src[t];
    } else {
        float4 z = make_float4(0.f, 0.f, 0.f, 0.f);
        ((float4*)(out + (size_t)n * ND))[t] = z;
    }
}

// ---------------- tiled fp32 grouped GEMM (128x128x8, 8x8 microtile) -------
__device__ __forceinline__ float gelu_exact(float v) {
    return 0.5f * v * (1.0f + erff(v * 0.70710678118654752f));
}

template<int KDIM, int NDIM, bool PHASE2>
__global__ __launch_bounds__(256, 2)
void sgemm_kernel(const float* __restrict__ W,
                  const float* __restrict__ bias,
                  float* __restrict__ out)
{
    const int BM = 128, BN = 128, BK = 8;
    __shared__ float As[BK][BM];
    __shared__ float Bs[BK][BN];
    int tid = threadIdx.x;
    int bm = blockIdx.y, bn = blockIdx.x;
    int e = bm / (CAP / BM);                 // 8 M-blocks per expert

    const float* A  = PHASE2 ? g_hbuf : g_xbuf;
    const float* Ae = A + (size_t)bm * BM * KDIM;
    const float* Be = W + (size_t)e * KDIM * NDIM + (size_t)bn * BN;

    int arow = tid >> 1, acol4 = (tid & 1) * 4;
    int brow = tid >> 5, bcol4 = (tid & 31) * 4;
    int tx = tid & 15, ty = tid >> 4;

    float acc[8][8];
    #pragma unroll
    for (int i = 0; i < 8; i++)
        #pragma unroll
        for (int j = 0; j < 8; j++) acc[i][j] = 0.f;

    for (int k0 = 0; k0 < KDIM; k0 += BK) {
        float4 av = *(const float4*)(Ae + (size_t)arow * KDIM + k0 + acol4);
        float4 bv = *(const float4*)(Be + (size_t)(k0 + brow) * NDIM + bcol4);
        As[acol4+0][arow] = av.x;
        As[acol4+1][arow] = av.y;
        As[acol4+2][arow] = av.z;
        As[acol4+3][arow] = av.w;
        *(float4*)&Bs[brow][bcol4] = bv;
        __syncthreads();
        #pragma unroll
        for (int kk = 0; kk < BK; kk++) {
            float a[8], b[8];
            *(float4*)(a)   = *(float4*)&As[kk][ty*8];
            *(float4*)(a+4) = *(float4*)&As[kk][ty*8+4];
            *(float4*)(b)   = *(float4*)&Bs[kk][tx*8];
            *(float4*)(b+4) = *(float4*)&Bs[kk][tx*8+4];
            #pragma unroll
            for (int i = 0; i < 8; i++)
                #pragma unroll
                for (int j = 0; j < 8; j++)
                    acc[i][j] += a[i] * b[j];
        }
        __syncthreads();
    }

    int gcol0 = bn * BN + tx * 8;
    const float* be = bias + (size_t)e * NDIM + gcol0;
    if (!PHASE2) {
        // epilogue: bias + exact GELU -> hbuf
        #pragma unroll
        for (int i = 0; i < 8; i++) {
            int grow = bm * BM + ty * 8 + i;
            float* crow = g_hbuf + (size_t)grow * NDIM + gcol0;
            #pragma unroll
            for (int j = 0; j < 8; j++) {
                float v = acc[i][j] + be[j];
                crow[j] = gelu_exact(v);
            }
        }
    } else {
        // epilogue: bias + scale, scatter to token rows of d_out
        #pragma unroll
        for (int i = 0; i < 8; i++) {
            int slot = bm * BM + ty * 8 + i;
            int tok = g_tok_of_slot[slot];
            if (tok >= 0) {
                float s = g_scale[tok];
                float* crow = out + (size_t)tok * NDIM + gcol0;
                #pragma unroll
                for (int j = 0; j < 8; j++)
                    crow[j] = (acc[i][j] + be[j]) * s;
            }
        }
    }
}

// ---------------- aux loss (deterministic reduction, 1 block) ---------------
__global__ void aux_kernel(float* __restrict__ out_aux)
{
    __shared__ float sh[256];
    int t = threadIdx.x;
    float ls = 0.f;
    for (int n = t; n < NTOK; n += 256) ls += g_lse2[n];
    float ps[NE] = {0,0,0,0,0,0,0,0};
    for (int n = t; n < NTOK; n += 256) {
        #pragma unroll
        for (int e = 0; e < NE; e++) ps[e] += g_probs[n*NE + e];
    }
    __shared__ float red[NE + 1];
    // reduce lse^2
    sh[t] = ls; __syncthreads();
    for (int o = 128; o > 0; o >>= 1) { if (t < o) sh[t] += sh[t + o]; __syncthreads(); }
    if (t == 0) red[NE] = sh[0];
    __syncthreads();
    for (int e = 0; e < NE; e++) {
        sh[t] = ps[e]; __syncthreads();
        for (int o = 128; o > 0; o >>= 1) { if (t < o) sh[t] += sh[t + o]; __syncthreads(); }
        if (t == 0) red[e] = sh[0];
        __syncthreads();
    }
    if (t == 0) {
        float invN = 1.0f / (float)NTOK;
        float fb = 0.f;
        for (int e = 0; e < NE; e++) {
            float f_i = (float)g_counts[e] * invN;
            float p_i = red[e] * invN;
            fb += f_i * p_i;
        }
        float z = red[NE] * invN;
        out_aux[0] = 0.01f * (float)NE * fb + 0.001f * z;
    }
}

// ---------------------------------------------------------------------------
extern "C" void kernel_launch(void* const* d_in, const int* in_sizes, int n_in,
                              void* d_out, int out_size)
{
    const float* x  = (const float*)d_in[0];
    const float* Wg = (const float*)d_in[1];
    const float* W1 = (const float*)d_in[2];
    const float* b1 = (const float*)d_in[3];
    const float* W2 = (const float*)d_in[4];
    const float* b2 = (const float*)d_in[5];
    float* out = (float*)d_out;

    router_kernel<<<NTOK/8, 256>>>(x, Wg);
    rank_kernel<<<1, 1024>>>();
    gather_kernel<<<NTOK, 256>>>(x, out);

    // GEMM1: [MT,1024] @ [1024,4096] + b1 -> gelu -> hbuf
    sgemm_kernel<ND, NH, false><<<dim3(NH/128, MT/128), 256>>>(W1, b1, out);
    // GEMM2: [MT,4096] @ [4096,1024] + b2 -> *scale -> scatter to out
    sgemm_kernel<NH, ND, true><<<dim3(ND/128, MT/128), 256>>>(W2, b2, out);

    if (out_size > NTOK * ND) {
        aux_kernel<<<1, 256>>>(out + (size_t)NTOK * ND);
    }
}

// round 5
// speedup vs baseline: 2.2772x; 2.2772x over previous
#include <cuda_runtime.h>
#include <cuda_bf16.h>
#include <math.h>
#include <stdint.h>

// Problem constants (fixed for MixtureOfExperts_498216206779)
#define NB 4
#define NT 2048
#define ND 1024
#define NH 4096
#define NE 8
#define NTOK (NB*NT)          // 8192
#define CAP 1024
#define MT (NE*CAP)           // 8192

// ---------------- scratch (device globals; no allocation allowed) ----------
__device__ float g_probs[NTOK*NE];
__device__ float g_lse2[NTOK];
__device__ int   g_expidx[NTOK];
__device__ float g_expprob[NTOK];
__device__ int   g_rank[NTOK];
__device__ int   g_sorted_tok[NTOK];
__device__ int   g_counts[NE];
__device__ int   g_tok_of_slot[MT];
__device__ float g_scale[NTOK];
// bf16 hi/lo split buffers
__device__ __nv_bfloat16 g_xh[(size_t)MT*ND],  g_xl[(size_t)MT*ND];    // tokens [M][K]
__device__ __nv_bfloat16 g_hh[(size_t)MT*NH],  g_hl[(size_t)MT*NH];    // hidden [M][K]
__device__ __nv_bfloat16 g_w1h[(size_t)NE*ND*NH], g_w1l[(size_t)NE*ND*NH]; // [E][N=NH][K=ND]
__device__ __nv_bfloat16 g_w2h[(size_t)NE*NH*ND], g_w2l[(size_t)NE*NH*ND]; // [E][N=ND][K=NH]

__device__ __forceinline__ uint32_t smem_u32(const void* p) {
    return (uint32_t)__cvta_generic_to_shared((void*)p);
}

// ---------------- router: logits, softmax, argmax, lse^2 -------------------
__global__ void router_kernel(const float* __restrict__ x,
                              const float* __restrict__ Wg)
{
    int warp = (blockIdx.x * blockDim.x + threadIdx.x) >> 5;
    int lane = threadIdx.x & 31;
    if (warp >= NTOK) return;
    const float* xr = x + (size_t)warp * ND;
    float acc[NE] = {0,0,0,0,0,0,0,0};
    for (int d = lane; d < ND; d += 32) {
        float xv = xr[d];
        const float* wr = Wg + d * NE;
        #pragma unroll
        for (int e = 0; e < NE; e++) acc[e] += xv * wr[e];
    }
    #pragma unroll
    for (int e = 0; e < NE; e++) {
        #pragma unroll
        for (int o = 16; o > 0; o >>= 1)
            acc[e] += __shfl_xor_sync(0xFFFFFFFFu, acc[e], o);
    }
    if (lane == 0) {
        float m = acc[0]; int am = 0;
        #pragma unroll
        for (int e = 1; e < NE; e++) if (acc[e] > m) { m = acc[e]; am = e; }
        float pe[NE]; float s = 0.f;
        #pragma unroll
        for (int e = 0; e < NE; e++) { pe[e] = expf(acc[e] - m); s += pe[e]; }
        float inv = 1.0f / s;
        #pragma unroll
        for (int e = 0; e < NE; e++) g_probs[warp*NE + e] = pe[e] * inv;
        float lse = logf(s) + m;
        g_lse2[warp]    = lse * lse;
        g_expidx[warp]  = am;
        g_expprob[warp] = pe[am] * inv;
    }
}

// ---------------- stable ranks via packed prefix scan (1 block) -------------
__global__ void rank_kernel()
{
    __shared__ unsigned long long h0[1024], h1[1024];
    __shared__ int stotal[NE], sstart[NE];
    int t = threadIdx.x;
    int base = t * 8;
    int e_arr[8];
    int cnt[NE] = {0,0,0,0,0,0,0,0};
    #pragma unroll
    for (int i = 0; i < 8; i++) { int e = g_expidx[base+i]; e_arr[i] = e; cnt[e]++; }
    unsigned long long p0 = 0, p1 = 0;
    #pragma unroll
    for (int e = 0; e < 4; e++) {
        p0 |= (unsigned long long)cnt[e]   << (16*e);
        p1 |= (unsigned long long)cnt[e+4] << (16*e);
    }
    h0[t] = p0; h1[t] = p1;
    __syncthreads();
    for (int off = 1; off < 1024; off <<= 1) {
        unsigned long long v0 = (t >= off) ? h0[t-off] : 0ULL;
        unsigned long long v1 = (t >= off) ? h1[t-off] : 0ULL;
        __syncthreads();
        h0[t] += v0; h1[t] += v1;
        __syncthreads();
    }
    unsigned long long inc0 = h0[t], inc1 = h1[t];
    if (t == 1023) {
        #pragma unroll
        for (int e = 0; e < 4; e++) {
            stotal[e]   = (int)((inc0 >> (16*e)) & 0xFFFF);
            stotal[e+4] = (int)((inc1 >> (16*e)) & 0xFFFF);
        }
    }
    for (int i = t; i < MT; i += 1024) g_tok_of_slot[i] = -1;
    __syncthreads();
    if (t == 0) { int s = 0; for (int e = 0; e < NE; e++) { sstart[e] = s; s += stotal[e]; } }
    if (t < NE) g_counts[t] = stotal[t];
    __syncthreads();
    int loc[NE];
    #pragma unroll
    for (int e = 0; e < 4; e++) {
        loc[e]   = (int)((inc0 >> (16*e)) & 0xFFFF) - cnt[e];
        loc[e+4] = (int)((inc1 >> (16*e)) & 0xFFFF) - cnt[e+4];
    }
    #pragma unroll
    for (int i = 0; i < 8; i++) {
        int n = base + i, e = e_arr[i];
        int r = loc[e]++;
        g_rank[n] = r;
        g_sorted_tok[sstart[e] + r] = n;
        if (r < CAP) g_tok_of_slot[e*CAP + r] = n;
    }
}

// ------------- gather tokens -> bf16 hi/lo expert buffers ------------------
__global__ void gather_kernel(const float* __restrict__ x, float* __restrict__ out)
{
    int n = blockIdx.x;
    int t = threadIdx.x;   // 256
    int e = g_expidx[n];
    int r = g_rank[n];
    if (t == 0) g_scale[n] = g_expprob[g_sorted_tok[n]];
    if (r < CAP) {
        size_t base = ((size_t)(e*CAP + r)) * ND + t*4;
        float4 v = ((const float4*)(x + (size_t)n * ND))[t];
        float vv[4] = {v.x, v.y, v.z, v.w};
        #pragma unroll
        for (int j = 0; j < 4; j++) {
            __nv_bfloat16 h = __float2bfloat16(vv[j]);
            g_xh[base + j] = h;
            g_xl[base + j] = __float2bfloat16(vv[j] - __bfloat162float(h));
        }
    } else {
        float4 z = make_float4(0.f, 0.f, 0.f, 0.f);
        ((float4*)(out + (size_t)n * ND))[t] = z;
    }
}

// ------------- weight transpose + bf16 hi/lo split: [E][K][N]->[E][N][K] ---
template<int K, int N>
__global__ void wconv_kernel(const float* __restrict__ W,
                             __nv_bfloat16* __restrict__ Wh,
                             __nv_bfloat16* __restrict__ Wl)
{
    __shared__ float tile[32][33];
    int e = blockIdx.z;
    int n0 = blockIdx.x * 32, k0 = blockIdx.y * 32;
    const float* We = W + (size_t)e * K * N;
    int tx = threadIdx.x, ty = threadIdx.y;   // (32, 8)
    #pragma unroll
    for (int i = 0; i < 4; i++) {
        int k = k0 + ty + i*8;
        tile[ty + i*8][tx] = We[(size_t)k * N + n0 + tx];
    }
    __syncthreads();
    __nv_bfloat16* Whe = Wh + (size_t)e * K * N;
    __nv_bfloat16* Wle = Wl + (size_t)e * K * N;
    #pragma unroll
    for (int i = 0; i < 4; i++) {
        int n = n0 + ty + i*8;
        float v = tile[tx][ty + i*8];
        __nv_bfloat16 h = __float2bfloat16(v);
        Whe[(size_t)n * K + k0 + tx] = h;
        Wle[(size_t)n * K + k0 + tx] = __float2bfloat16(v - __bfloat162float(h));
    }
}

// ================== mma.sync bf16x3 grouped GEMM ===========================
__device__ __forceinline__ float gelu_exact(float v) {
    return 0.5f * v * (1.0f + erff(v * 0.70710678118654752f));
}

#define CP_ASYNC16(dst, src) \
    asm volatile("cp.async.cg.shared.global [%0], [%1], 16;" :: "r"(dst), "l"(src))
#define CP_COMMIT() asm volatile("cp.async.commit_group;" ::: "memory")
#define CP_WAIT0()  asm volatile("cp.async.wait_group 0;" ::: "memory")

__device__ __forceinline__ void ldsm4(uint32_t* r, uint32_t addr) {
    asm volatile("ldmatrix.sync.aligned.m8n8.x4.shared.b16 {%0,%1,%2,%3}, [%4];"
                 : "=r"(r[0]), "=r"(r[1]), "=r"(r[2]), "=r"(r[3]) : "r"(addr));
}
__device__ __forceinline__ void mma16816(float* d, const uint32_t* a, const uint32_t* b) {
    asm volatile(
        "mma.sync.aligned.m16n8k16.row.col.f32.bf16.bf16.f32 "
        "{%0,%1,%2,%3}, {%4,%5,%6,%7}, {%8,%9}, {%0,%1,%2,%3};"
        : "+f"(d[0]), "+f"(d[1]), "+f"(d[2]), "+f"(d[3])
        : "r"(a[0]), "r"(a[1]), "r"(a[2]), "r"(a[3]), "r"(b[0]), "r"(b[1]));
}

// SMEM: 2 stages x 4 matrices (Ah, Al, Bh, Bl), each 128 rows x 80B pitch
// (32 bf16 data = 64B + 16B pad -> conflict-free ldmatrix).
#define PITCH 80
#define MATB  (128 * PITCH)        // 10240
#define STAGEB (4 * MATB)          // 40960
#define GSMEM (2 * STAGEB)         // 81920

template<int KTOT, int NTOT, bool PHASE2>
__global__ __launch_bounds__(256, 1)
void tgemm_kernel(const __nv_bfloat16* __restrict__ Ah_g,
                  const __nv_bfloat16* __restrict__ Al_g,
                  const __nv_bfloat16* __restrict__ Bh_g,
                  const __nv_bfloat16* __restrict__ Bl_g,
                  const float* __restrict__ bias,
                  float* __restrict__ outp)
{
    extern __shared__ char smem[];
    uint32_t sbase = smem_u32(smem);
    int tid = threadIdx.x;
    int wid = tid >> 5, lane = tid & 31;
    int wm = wid & 3, wn = wid >> 2;          // warp grid 4(M) x 2(N)
    int bn = blockIdx.x, bm = blockIdx.y;
    int e = bm >> 3;                          // 8 M-blocks per expert

    const __nv_bfloat16* Aeh = Ah_g + (size_t)bm * 128 * KTOT;
    const __nv_bfloat16* Ael = Al_g + (size_t)bm * 128 * KTOT;
    const __nv_bfloat16* Beh = Bh_g + (size_t)e * NTOT * KTOT + (size_t)bn * 128 * KTOT;
    const __nv_bfloat16* Bel = Bl_g + (size_t)e * NTOT * KTOT + (size_t)bn * 128 * KTOT;

    float acc[2][8][4];
    #pragma unroll
    for (int i = 0; i < 2; i++)
        #pragma unroll
        for (int j = 0; j < 8; j++)
            #pragma unroll
            for (int c = 0; c < 4; c++) acc[i][j][c] = 0.f;

    const int S = KTOT / 32;

    // row/chunk for this thread's cp.async slots (2 reps x 4 matrices)
    int r0 = tid >> 2, c0 = tid & 3;          // rep 0: rows 0..63
    int r1 = r0 + 64;                          // rep 1: rows 64..127

    auto load_stage = [&](int s, int buf) {
        int k0 = s * 32;
        uint32_t sb = sbase + buf * STAGEB;
        const __nv_bfloat16* gA_h = Aeh + (size_t)r0 * KTOT + k0 + c0 * 8;
        const __nv_bfloat16* gA_l = Ael + (size_t)r0 * KTOT + k0 + c0 * 8;
        const __nv_bfloat16* gB_h = Beh + (size_t)r0 * KTOT + k0 + c0 * 8;
        const __nv_bfloat16* gB_l = Bel + (size_t)r0 * KTOT + k0 + c0 * 8;
        uint32_t so = r0 * PITCH + c0 * 16;
        CP_ASYNC16(sb + so,            gA_h);
        CP_ASYNC16(sb + MATB + so,     gA_l);
        CP_ASYNC16(sb + 2*MATB + so,   gB_h);
        CP_ASYNC16(sb + 3*MATB + so,   gB_l);
        size_t gstep = (size_t)64 * KTOT;
        uint32_t sstep = 64 * PITCH;
        CP_ASYNC16(sb + so + sstep,          gA_h + gstep);
        CP_ASYNC16(sb + MATB + so + sstep,   gA_l + gstep);
        CP_ASYNC16(sb + 2*MATB + so + sstep, gB_h + gstep);
        CP_ASYNC16(sb + 3*MATB + so + sstep, gB_l + gstep);
        CP_COMMIT();
    };

    // ldmatrix lane decomposition
    int lr = lane & 7, lq = (lane >> 3) & 1, lh = lane >> 4;

    load_stage(0, 0);
    int buf = 0;
    for (int s = 0; s < S; s++) {
        CP_WAIT0();
        __syncthreads();
        if (s + 1 < S) load_stage(s + 1, buf ^ 1);

        uint32_t sb = sbase + buf * STAGEB;
        #pragma unroll
        for (int kk = 0; kk < 2; kk++) {
            uint32_t ah[2][4], al[2][4], bh[8][2], bl[8][2];
            #pragma unroll
            for (int mi = 0; mi < 2; mi++) {
                int row = wm*32 + mi*16 + lr + lq*8;
                uint32_t off = row * PITCH + kk*32 + lh*16;
                ldsm4(ah[mi], sb + off);
                ldsm4(al[mi], sb + MATB + off);
            }
            #pragma unroll
            for (int nj2 = 0; nj2 < 4; nj2++) {
                int row = wn*64 + nj2*16 + lr + lh*8;
                uint32_t off = row * PITCH + kk*32 + lq*16;
                uint32_t t[4];
                ldsm4(t, sb + 2*MATB + off);
                bh[2*nj2][0] = t[0]; bh[2*nj2][1] = t[1];
                bh[2*nj2+1][0] = t[2]; bh[2*nj2+1][1] = t[3];
                ldsm4(t, sb + 3*MATB + off);
                bl[2*nj2][0] = t[0]; bl[2*nj2][1] = t[1];
                bl[2*nj2+1][0] = t[2]; bl[2*nj2+1][1] = t[3];
            }
            #pragma unroll
            for (int mi = 0; mi < 2; mi++)
                #pragma unroll
                for (int nj = 0; nj < 8; nj++) {
                    mma16816(acc[mi][nj], ah[mi], bh[nj]);
                    mma16816(acc[mi][nj], ah[mi], bl[nj]);
                    mma16816(acc[mi][nj], al[mi], bh[nj]);
                }
        }
        __syncthreads();
        buf ^= 1;
    }

    // ---------------- epilogue --------------------------------------------
    int qr = lane >> 2, qc = lane & 3;
    float2 bv[8];
    #pragma unroll
    for (int nj = 0; nj < 8; nj++) {
        int colg = bn*128 + wn*64 + nj*8 + 2*qc;
        bv[nj] = *(const float2*)(bias + (size_t)e * NTOT + colg);
    }
    if (!PHASE2) {
        #pragma unroll
        for (int mi = 0; mi < 2; mi++)
            #pragma unroll
            for (int h = 0; h < 2; h++) {
                int rowg = bm*128 + wm*32 + mi*16 + qr + h*8;
                #pragma unroll
                for (int nj = 0; nj < 8; nj++) {
                    int colg = bn*128 + wn*64 + nj*8 + 2*qc;
                    float v0 = acc[mi][nj][2*h]   + bv[nj].x;
                    float v1 = acc[mi][nj][2*h+1] + bv[nj].y;
                    float gg0 = gelu_exact(v0), gg1 = gelu_exact(v1);
                    __nv_bfloat16 h0 = __float2bfloat16(gg0);
                    __nv_bfloat16 h1 = __float2bfloat16(gg1);
                    __nv_bfloat162 hv; hv.x = h0; hv.y = h1;
                    __nv_bfloat162 lv;
                    lv.x = __float2bfloat16(gg0 - __bfloat162float(h0));
                    lv.y = __float2bfloat16(gg1 - __bfloat162float(h1));
                    *(__nv_bfloat162*)(g_hh + (size_t)rowg * NTOT + colg) = hv;
                    *(__nv_bfloat162*)(g_hl + (size_t)rowg * NTOT + colg) = lv;
                }
            }
    } else {
        #pragma unroll
        for (int mi = 0; mi < 2; mi++)
            #pragma unroll
            for (int h = 0; h < 2; h++) {
                int slot = bm*128 + wm*32 + mi*16 + qr + h*8;
                int tok = g_tok_of_slot[slot];
                if (tok >= 0) {
                    float sc = g_scale[tok];
                    float* orow = outp + (size_t)tok * NTOT;
                    #pragma unroll
                    for (int nj = 0; nj < 8; nj++) {
                        int colg = bn*128 + wn*64 + nj*8 + 2*qc;
                        float2 ov;
                        ov.x = (acc[mi][nj][2*h]   + bv[nj].x) * sc;
                        ov.y = (acc[mi][nj][2*h+1] + bv[nj].y) * sc;
                        *(float2*)(orow + colg) = ov;
                    }
                }
            }
    }
}

// ---------------- aux loss (deterministic reduction, 1 block) ---------------
__global__ void aux_kernel(float* __restrict__ out_aux)
{
    __shared__ float sh[256];
    int t = threadIdx.x;
    float ls = 0.f;
    for (int n = t; n < NTOK; n += 256) ls += g_lse2[n];
    float ps[NE] = {0,0,0,0,0,0,0,0};
    for (int n = t; n < NTOK; n += 256) {
        #pragma unroll
        for (int e = 0; e < NE; e++) ps[e] += g_probs[n*NE + e];
    }
    __shared__ float red[NE + 1];
    sh[t] = ls; __syncthreads();
    for (int o = 128; o > 0; o >>= 1) { if (t < o) sh[t] += sh[t + o]; __syncthreads(); }
    if (t == 0) red[NE] = sh[0];
    __syncthreads();
    for (int e = 0; e < NE; e++) {
        sh[t] = ps[e]; __syncthreads();
        for (int o = 128; o > 0; o >>= 1) { if (t < o) sh[t] += sh[t + o]; __syncthreads(); }
        if (t == 0) red[e] = sh[0];
        __syncthreads();
    }
    if (t == 0) {
        float invN = 1.0f / (float)NTOK;
        float fb = 0.f;
        for (int e = 0; e < NE; e++) {
            float f_i = (float)g_counts[e] * invN;
            float p_i = red[e] * invN;
            fb += f_i * p_i;
        }
        float z = red[NE] * invN;
        out_aux[0] = 0.01f * (float)NE * fb + 0.001f * z;
    }
}

// ---------------------------------------------------------------------------
extern "C" void kernel_launch(void* const* d_in, const int* in_sizes, int n_in,
                              void* d_out, int out_size)
{
    const float* x  = (const float*)d_in[0];
    const float* Wg = (const float*)d_in[1];
    const float* W1 = (const float*)d_in[2];
    const float* b1 = (const float*)d_in[3];
    const float* W2 = (const float*)d_in[4];
    const float* b2 = (const float*)d_in[5];
    float* out = (float*)d_out;

    cudaFuncSetAttribute(tgemm_kernel<ND, NH, false>,
                         cudaFuncAttributeMaxDynamicSharedMemorySize, GSMEM);
    cudaFuncSetAttribute(tgemm_kernel<NH, ND, true>,
                         cudaFuncAttributeMaxDynamicSharedMemorySize, GSMEM);

    __nv_bfloat16 *xh, *xl, *hh, *hl, *w1h, *w1l, *w2h, *w2l;
    cudaGetSymbolAddress((void**)&xh,  g_xh);
    cudaGetSymbolAddress((void**)&xl,  g_xl);
    cudaGetSymbolAddress((void**)&hh,  g_hh);
    cudaGetSymbolAddress((void**)&hl,  g_hl);
    cudaGetSymbolAddress((void**)&w1h, g_w1h);
    cudaGetSymbolAddress((void**)&w1l, g_w1l);
    cudaGetSymbolAddress((void**)&w2h, g_w2h);
    cudaGetSymbolAddress((void**)&w2l, g_w2l);

    router_kernel<<<NTOK/8, 256>>>(x, Wg);
    rank_kernel<<<1, 1024>>>();
    gather_kernel<<<NTOK, 256>>>(x, out);

    // weight transpose + split
    wconv_kernel<ND, NH><<<dim3(NH/32, ND/32, NE), dim3(32, 8)>>>(W1, w1h, w1l);
    wconv_kernel<NH, ND><<<dim3(ND/32, NH/32, NE), dim3(32, 8)>>>(W2, w2h, w2l);

    // GEMM1: [MT,ND] @ W1t -> gelu -> hidden(hi/lo)
    tgemm_kernel<ND, NH, false><<<dim3(NH/128, MT/128), 256, GSMEM>>>(
        xh, xl, w1h, w1l, b1, out);
    // GEMM2: [MT,NH] @ W2t -> bias + scale -> scatter to out
    tgemm_kernel<NH, ND, true><<<dim3(ND/128, MT/128), 256, GSMEM>>>(
        hh, hl, w2h, w2l, b2, out);

    if (out_size > NTOK * ND) {
        aux_kernel<<<1, 256>>>(out + (size_t)NTOK * ND);
    }
}

// round 6
// speedup vs baseline: 3.5940x; 1.5783x over previous
#include <cuda_runtime.h>
#include <cuda_fp16.h>
#include <math.h>
#include <stdint.h>

// Problem constants (fixed for MixtureOfExperts_498216206779)
#define NB 4
#define NT 2048
#define ND 1024
#define NH 4096
#define NE 8
#define NTOK (NB*NT)          // 8192
#define CAP 1024
#define MT (NE*CAP)           // 8192

// ---------------- scratch (device globals; no allocation allowed) ----------
__device__ float g_probs[NTOK*NE];
__device__ float g_lse2[NTOK];
__device__ int   g_expidx[NTOK];
__device__ float g_expprob[NTOK];
__device__ int   g_rank[NTOK];
__device__ int   g_sorted_tok[NTOK];
__device__ int   g_counts[NE];
__device__ int   g_tok_of_slot[MT];
__device__ float g_scale[NTOK];
// fp16 split buffers: A-side hi/lo, B-side (weights) hi only
__device__ __half g_xh[(size_t)MT*ND],  g_xl[(size_t)MT*ND];    // tokens [M][K]
__device__ __half g_hh[(size_t)MT*NH],  g_hl[(size_t)MT*NH];    // hidden [M][K]
__device__ __half g_w1h[(size_t)NE*ND*NH];  // [E][N=NH][K=ND]
__device__ __half g_w2h[(size_t)NE*NH*ND];  // [E][N=ND][K=NH]

__device__ __forceinline__ uint32_t smem_u32(const void* p) {
    return (uint32_t)__cvta_generic_to_shared((void*)p);
}

// ---------------- router: logits, softmax, argmax, lse^2 -------------------
__global__ void router_kernel(const float* __restrict__ x,
                              const float* __restrict__ Wg)
{
    int warp = (blockIdx.x * blockDim.x + threadIdx.x) >> 5;
    int lane = threadIdx.x & 31;
    if (warp >= NTOK) return;
    const float* xr = x + (size_t)warp * ND;
    float acc[NE] = {0,0,0,0,0,0,0,0};
    for (int d = lane; d < ND; d += 32) {
        float xv = xr[d];
        const float* wr = Wg + d * NE;
        #pragma unroll
        for (int e = 0; e < NE; e++) acc[e] += xv * wr[e];
    }
    #pragma unroll
    for (int e = 0; e < NE; e++) {
        #pragma unroll
        for (int o = 16; o > 0; o >>= 1)
            acc[e] += __shfl_xor_sync(0xFFFFFFFFu, acc[e], o);
    }
    if (lane == 0) {
        float m = acc[0]; int am = 0;
        #pragma unroll
        for (int e = 1; e < NE; e++) if (acc[e] > m) { m = acc[e]; am = e; }
        float pe[NE]; float s = 0.f;
        #pragma unroll
        for (int e = 0; e < NE; e++) { pe[e] = expf(acc[e] - m); s += pe[e]; }
        float inv = 1.0f / s;
        #pragma unroll
        for (int e = 0; e < NE; e++) g_probs[warp*NE + e] = pe[e] * inv;
        float lse = logf(s) + m;
        g_lse2[warp]    = lse * lse;
        g_expidx[warp]  = am;
        g_expprob[warp] = pe[am] * inv;
    }
}

// ---------------- stable ranks via packed prefix scan (1 block) -------------
__global__ void rank_kernel()
{
    __shared__ unsigned long long h0[1024], h1[1024];
    __shared__ int stotal[NE], sstart[NE];
    int t = threadIdx.x;
    int base = t * 8;
    int e_arr[8];
    int cnt[NE] = {0,0,0,0,0,0,0,0};
    #pragma unroll
    for (int i = 0; i < 8; i++) { int e = g_expidx[base+i]; e_arr[i] = e; cnt[e]++; }
    unsigned long long p0 = 0, p1 = 0;
    #pragma unroll
    for (int e = 0; e < 4; e++) {
        p0 |= (unsigned long long)cnt[e]   << (16*e);
        p1 |= (unsigned long long)cnt[e+4] << (16*e);
    }
    h0[t] = p0; h1[t] = p1;
    __syncthreads();
    for (int off = 1; off < 1024; off <<= 1) {
        unsigned long long v0 = (t >= off) ? h0[t-off] : 0ULL;
        unsigned long long v1 = (t >= off) ? h1[t-off] : 0ULL;
        __syncthreads();
        h0[t] += v0; h1[t] += v1;
        __syncthreads();
    }
    unsigned long long inc0 = h0[t], inc1 = h1[t];
    if (t == 1023) {
        #pragma unroll
        for (int e = 0; e < 4; e++) {
            stotal[e]   = (int)((inc0 >> (16*e)) & 0xFFFF);
            stotal[e+4] = (int)((inc1 >> (16*e)) & 0xFFFF);
        }
    }
    for (int i = t; i < MT; i += 1024) g_tok_of_slot[i] = -1;
    __syncthreads();
    if (t == 0) { int s = 0; for (int e = 0; e < NE; e++) { sstart[e] = s; s += stotal[e]; } }
    if (t < NE) g_counts[t] = stotal[t];
    __syncthreads();
    int loc[NE];
    #pragma unroll
    for (int e = 0; e < 4; e++) {
        loc[e]   = (int)((inc0 >> (16*e)) & 0xFFFF) - cnt[e];
        loc[e+4] = (int)((inc1 >> (16*e)) & 0xFFFF) - cnt[e+4];
    }
    #pragma unroll
    for (int i = 0; i < 8; i++) {
        int n = base + i, e = e_arr[i];
        int r = loc[e]++;
        g_rank[n] = r;
        g_sorted_tok[sstart[e] + r] = n;
        if (r < CAP) g_tok_of_slot[e*CAP + r] = n;
    }
}

// ------------- gather tokens -> fp16 hi/lo expert buffers ------------------
__global__ void gather_kernel(const float* __restrict__ x, float* __restrict__ out)
{
    int n = blockIdx.x;
    int t = threadIdx.x;   // 256
    int e = g_expidx[n];
    int r = g_rank[n];
    if (t == 0) g_scale[n] = g_expprob[g_sorted_tok[n]];
    if (r < CAP) {
        size_t base = ((size_t)(e*CAP + r)) * ND + t*4;
        float4 v = ((const float4*)(x + (size_t)n * ND))[t];
        float vv[4] = {v.x, v.y, v.z, v.w};
        #pragma unroll
        for (int j = 0; j < 4; j++) {
            __half h = __float2half(vv[j]);
            g_xh[base + j] = h;
            g_xl[base + j] = __float2half(vv[j] - __half2float(h));
        }
    } else {
        float4 z = make_float4(0.f, 0.f, 0.f, 0.f);
        ((float4*)(out + (size_t)n * ND))[t] = z;
    }
}

// ------------- weight transpose + fp16 convert: [E][K][N] -> [E][N][K] -----
template<int K, int N>
__global__ void wconv_kernel(const float* __restrict__ W,
                             __half* __restrict__ Wh)
{
    __shared__ float tile[32][33];
    int e = blockIdx.z;
    int n0 = blockIdx.x * 32, k0 = blockIdx.y * 32;
    const float* We = W + (size_t)e * K * N;
    int tx = threadIdx.x, ty = threadIdx.y;   // (32, 8)
    #pragma unroll
    for (int i = 0; i < 4; i++) {
        int k = k0 + ty + i*8;
        tile[ty + i*8][tx] = We[(size_t)k * N + n0 + tx];
    }
    __syncthreads();
    __half* Whe = Wh + (size_t)e * K * N;
    #pragma unroll
    for (int i = 0; i < 4; i++) {
        int n = n0 + ty + i*8;
        Whe[(size_t)n * K + k0 + tx] = __float2half(tile[tx][ty + i*8]);
    }
}

// ================== mma.sync fp16 2-pass grouped GEMM ======================
__device__ __forceinline__ float gelu_exact(float v) {
    return 0.5f * v * (1.0f + erff(v * 0.70710678118654752f));
}

#define CP_ASYNC16(dst, src) \
    asm volatile("cp.async.cg.shared.global [%0], [%1], 16;" :: "r"(dst), "l"(src))
#define CP_COMMIT() asm volatile("cp.async.commit_group;" ::: "memory")
#define CP_WAIT0()  asm volatile("cp.async.wait_group 0;" ::: "memory")

__device__ __forceinline__ void ldsm4(uint32_t* r, uint32_t addr) {
    asm volatile("ldmatrix.sync.aligned.m8n8.x4.shared.b16 {%0,%1,%2,%3}, [%4];"
                 : "=r"(r[0]), "=r"(r[1]), "=r"(r[2]), "=r"(r[3]) : "r"(addr));
}
__device__ __forceinline__ void mma16816(float* d, const uint32_t* a, const uint32_t* b) {
    asm volatile(
        "mma.sync.aligned.m16n8k16.row.col.f32.f16.f16.f32 "
        "{%0,%1,%2,%3}, {%4,%5,%6,%7}, {%8,%9}, {%0,%1,%2,%3};"
        : "+f"(d[0]), "+f"(d[1]), "+f"(d[2]), "+f"(d[3])
        : "r"(a[0]), "r"(a[1]), "r"(a[2]), "r"(a[3]), "r"(b[0]), "r"(b[1]));
}

// SMEM: 2 stages x 3 matrices (Ah, Al, Bh), each 128 rows x 80B pitch
// (32 fp16 data = 64B + 16B pad -> conflict-free ldmatrix).
#define PITCH 80
#define MATB  (128 * PITCH)        // 10240
#define STAGEB (3 * MATB)          // 30720
#define GSMEM (2 * STAGEB)         // 61440

template<int KTOT, int NTOT, bool PHASE2>
__global__ __launch_bounds__(256, 2)
void tgemm_kernel(const __half* __restrict__ Ah_g,
                  const __half* __restrict__ Al_g,
                  const __half* __restrict__ Bh_g,
                  const float* __restrict__ bias,
                  float* __restrict__ outp)
{
    extern __shared__ char smem[];
    uint32_t sbase = smem_u32(smem);
    int tid = threadIdx.x;
    int wid = tid >> 5, lane = tid & 31;
    int wm = wid & 3, wn = wid >> 2;          // warp grid 4(M) x 2(N)
    int bn = blockIdx.x, bm = blockIdx.y;
    int e = bm >> 3;                          // 8 M-blocks per expert

    const __half* Aeh = Ah_g + (size_t)bm * 128 * KTOT;
    const __half* Ael = Al_g + (size_t)bm * 128 * KTOT;
    const __half* Beh = Bh_g + (size_t)e * NTOT * KTOT + (size_t)bn * 128 * KTOT;

    float acc[2][8][4];
    #pragma unroll
    for (int i = 0; i < 2; i++)
        #pragma unroll
        for (int j = 0; j < 8; j++)
            #pragma unroll
            for (int c = 0; c < 4; c++) acc[i][j][c] = 0.f;

    const int S = KTOT / 32;

    int r0 = tid >> 2, c0 = tid & 3;          // rows 0..63, 16B chunks

    auto load_stage = [&](int s, int buf) {
        int k0 = s * 32;
        uint32_t sb = sbase + buf * STAGEB;
        const __half* gA_h = Aeh + (size_t)r0 * KTOT + k0 + c0 * 8;
        const __half* gA_l = Ael + (size_t)r0 * KTOT + k0 + c0 * 8;
        const __half* gB_h = Beh + (size_t)r0 * KTOT + k0 + c0 * 8;
        uint32_t so = r0 * PITCH + c0 * 16;
        CP_ASYNC16(sb + so,            gA_h);
        CP_ASYNC16(sb + MATB + so,     gA_l);
        CP_ASYNC16(sb + 2*MATB + so,   gB_h);
        size_t gstep = (size_t)64 * KTOT;
        uint32_t sstep = 64 * PITCH;
        CP_ASYNC16(sb + so + sstep,          gA_h + gstep);
        CP_ASYNC16(sb + MATB + so + sstep,   gA_l + gstep);
        CP_ASYNC16(sb + 2*MATB + so + sstep, gB_h + gstep);
        CP_COMMIT();
    };

    // ldmatrix lane decomposition
    int lr = lane & 7, lq = (lane >> 3) & 1, lh = lane >> 4;

    load_stage(0, 0);
    int buf = 0;
    for (int s = 0; s < S; s++) {
        CP_WAIT0();
        __syncthreads();
        if (s + 1 < S) load_stage(s + 1, buf ^ 1);

        uint32_t sb = sbase + buf * STAGEB;
        #pragma unroll
        for (int kk = 0; kk < 2; kk++) {
            uint32_t ah[2][4], al[2][4], bh[8][2];
            #pragma unroll
            for (int mi = 0; mi < 2; mi++) {
                int row = wm*32 + mi*16 + lr + lq*8;
                uint32_t off = row * PITCH + kk*32 + lh*16;
                ldsm4(ah[mi], sb + off);
                ldsm4(al[mi], sb + MATB + off);
            }
            #pragma unroll
            for (int nj2 = 0; nj2 < 4; nj2++) {
                int row = wn*64 + nj2*16 + lr + lh*8;
                uint32_t off = row * PITCH + kk*32 + lq*16;
                uint32_t t[4];
                ldsm4(t, sb + 2*MATB + off);
                bh[2*nj2][0] = t[0]; bh[2*nj2][1] = t[1];
                bh[2*nj2+1][0] = t[2]; bh[2*nj2+1][1] = t[3];
            }
            #pragma unroll
            for (int mi = 0; mi < 2; mi++)
                #pragma unroll
                for (int nj = 0; nj < 8; nj++) {
                    mma16816(acc[mi][nj], ah[mi], bh[nj]);
                    mma16816(acc[mi][nj], al[mi], bh[nj]);
                }
        }
        __syncthreads();
        buf ^= 1;
    }

    // ---------------- epilogue --------------------------------------------
    int qr = lane >> 2, qc = lane & 3;
    float2 bv[8];
    #pragma unroll
    for (int nj = 0; nj < 8; nj++) {
        int colg = bn*128 + wn*64 + nj*8 + 2*qc;
        bv[nj] = *(const float2*)(bias + (size_t)e * NTOT + colg);
    }
    if (!PHASE2) {
        #pragma unroll
        for (int mi = 0; mi < 2; mi++)
            #pragma unroll
            for (int h = 0; h < 2; h++) {
                int rowg = bm*128 + wm*32 + mi*16 + qr + h*8;
                #pragma unroll
                for (int nj = 0; nj < 8; nj++) {
                    int colg = bn*128 + wn*64 + nj*8 + 2*qc;
                    float v0 = acc[mi][nj][2*h]   + bv[nj].x;
                    float v1 = acc[mi][nj][2*h+1] + bv[nj].y;
                    float gg0 = gelu_exact(v0), gg1 = gelu_exact(v1);
                    __half h0 = __float2half(gg0);
                    __half h1 = __float2half(gg1);
                    __half2 hv; hv.x = h0; hv.y = h1;
                    __half2 lv;
                    lv.x = __float2half(gg0 - __half2float(h0));
                    lv.y = __float2half(gg1 - __half2float(h1));
                    *(__half2*)(g_hh + (size_t)rowg * NTOT + colg) = hv;
                    *(__half2*)(g_hl + (size_t)rowg * NTOT + colg) = lv;
                }
            }
    } else {
        #pragma unroll
        for (int mi = 0; mi < 2; mi++)
            #pragma unroll
            for (int h = 0; h < 2; h++) {
                int slot = bm*128 + wm*32 + mi*16 + qr + h*8;
                int tok = g_tok_of_slot[slot];
                if (tok >= 0) {
                    float sc = g_scale[tok];
                    float* orow = outp + (size_t)tok * NTOT;
                    #pragma unroll
                    for (int nj = 0; nj < 8; nj++) {
                        int colg = bn*128 + wn*64 + nj*8 + 2*qc;
                        float2 ov;
                        ov.x = (acc[mi][nj][2*h]   + bv[nj].x) * sc;
                        ov.y = (acc[mi][nj][2*h+1] + bv[nj].y) * sc;
                        *(float2*)(orow + colg) = ov;
                    }
                }
            }
    }
}

// ---------------- aux loss (deterministic reduction, 1 block) ---------------
__global__ void aux_kernel(float* __restrict__ out_aux)
{
    __shared__ float sh[256];
    int t = threadIdx.x;
    float ls = 0.f;
    for (int n = t; n < NTOK; n += 256) ls += g_lse2[n];
    float ps[NE] = {0,0,0,0,0,0,0,0};
    for (int n = t; n < NTOK; n += 256) {
        #pragma unroll
        for (int e = 0; e < NE; e++) ps[e] += g_probs[n*NE + e];
    }
    __shared__ float red[NE + 1];
    sh[t] = ls; __syncthreads();
    for (int o = 128; o > 0; o >>= 1) { if (t < o) sh[t] += sh[t + o]; __syncthreads(); }
    if (t == 0) red[NE] = sh[0];
    __syncthreads();
    for (int e = 0; e < NE; e++) {
        sh[t] = ps[e]; __syncthreads();
        for (int o = 128; o > 0; o >>= 1) { if (t < o) sh[t] += sh[t + o]; __syncthreads(); }
        if (t == 0) red[e] = sh[0];
        __syncthreads();
    }
    if (t == 0) {
        float invN = 1.0f / (float)NTOK;
        float fb = 0.f;
        for (int e = 0; e < NE; e++) {
            float f_i = (float)g_counts[e] * invN;
            float p_i = red[e] * invN;
            fb += f_i * p_i;
        }
        float z = red[NE] * invN;
        out_aux[0] = 0.01f * (float)NE * fb + 0.001f * z;
    }
}

// ---------------------------------------------------------------------------
extern "C" void kernel_launch(void* const* d_in, const int* in_sizes, int n_in,
                              void* d_out, int out_size)
{
    const float* x  = (const float*)d_in[0];
    const float* Wg = (const float*)d_in[1];
    const float* W1 = (const float*)d_in[2];
    const float* b1 = (const float*)d_in[3];
    const float* W2 = (const float*)d_in[4];
    const float* b2 = (const float*)d_in[5];
    float* out = (float*)d_out;

    cudaFuncSetAttribute(tgemm_kernel<ND, NH, false>,
                         cudaFuncAttributeMaxDynamicSharedMemorySize, GSMEM);
    cudaFuncSetAttribute(tgemm_kernel<NH, ND, true>,
                         cudaFuncAttributeMaxDynamicSharedMemorySize, GSMEM);

    __half *xh, *xl, *hh, *hl, *w1h, *w2h;
    cudaGetSymbolAddress((void**)&xh,  g_xh);
    cudaGetSymbolAddress((void**)&xl,  g_xl);
    cudaGetSymbolAddress((void**)&hh,  g_hh);
    cudaGetSymbolAddress((void**)&hl,  g_hl);
    cudaGetSymbolAddress((void**)&w1h, g_w1h);
    cudaGetSymbolAddress((void**)&w2h, g_w2h);

    router_kernel<<<NTOK/8, 256>>>(x, Wg);
    rank_kernel<<<1, 1024>>>();
    gather_kernel<<<NTOK, 256>>>(x, out);

    // weight transpose + fp16 convert
    wconv_kernel<ND, NH><<<dim3(NH/32, ND/32, NE), dim3(32, 8)>>>(W1, w1h);
    wconv_kernel<NH, ND><<<dim3(ND/32, NH/32, NE), dim3(32, 8)>>>(W2, w2h);

    // GEMM1: [MT,ND] @ W1t -> gelu -> hidden(hi/lo)
    tgemm_kernel<ND, NH, false><<<dim3(NH/128, MT/128), 256, GSMEM>>>(
        xh, xl, w1h, b1, out);
    // GEMM2: [MT,NH] @ W2t -> bias + scale -> scatter to out
    tgemm_kernel<NH, ND, true><<<dim3(ND/128, MT/128), 256, GSMEM>>>(
        hh, hl, w2h, b2, out);

    if (out_size > NTOK * ND) {
        aux_kernel<<<1, 256>>>(out + (size_t)NTOK * ND);
    }
}

// round 7
// speedup vs baseline: 5.3357x; 1.4846x over previous
#include <cuda_runtime.h>
#include <cuda_fp16.h>
#include <math.h>
#include <stdint.h>

// Problem constants (fixed for MixtureOfExperts_498216206779)
#define NB 4
#define NT 2048
#define ND 1024
#define NH 4096
#define NE 8
#define NTOK (NB*NT)          // 8192
#define CAP 1024
#define MT (NE*CAP)           // 8192

// ---------------- scratch (device globals; no allocation allowed) ----------
__device__ float g_probs[NTOK*NE];
__device__ float g_lse2[NTOK];
__device__ int   g_expidx[NTOK];
__device__ float g_expprob[NTOK];
__device__ int   g_rank[NTOK];
__device__ int   g_sorted_tok[NTOK];
__device__ int   g_counts[NE];
__device__ int   g_tok_of_slot[MT];
__device__ float g_scale[NTOK];
// fp16 buffers (single precision pass; error budget ~4.2e-4 < 1e-3)
__device__ __half g_xh[(size_t)MT*ND];      // tokens [M][K]
__device__ __half g_hh[(size_t)MT*NH];      // hidden [M][K]
__device__ __half g_w1h[(size_t)NE*ND*NH];  // [E][N=NH][K=ND]
__device__ __half g_w2h[(size_t)NE*NH*ND];  // [E][N=ND][K=NH]

__device__ __forceinline__ uint32_t smem_u32(const void* p) {
    return (uint32_t)__cvta_generic_to_shared((void*)p);
}

// ---------------- router: logits, softmax, argmax, lse^2 -------------------
__global__ void router_kernel(const float* __restrict__ x,
                              const float* __restrict__ Wg)
{
    int warp = (blockIdx.x * blockDim.x + threadIdx.x) >> 5;
    int lane = threadIdx.x & 31;
    if (warp >= NTOK) return;
    const float* xr = x + (size_t)warp * ND;
    float acc[NE] = {0,0,0,0,0,0,0,0};
    for (int d = lane; d < ND; d += 32) {
        float xv = xr[d];
        const float* wr = Wg + d * NE;
        #pragma unroll
        for (int e = 0; e < NE; e++) acc[e] += xv * wr[e];
    }
    #pragma unroll
    for (int e = 0; e < NE; e++) {
        #pragma unroll
        for (int o = 16; o > 0; o >>= 1)
            acc[e] += __shfl_xor_sync(0xFFFFFFFFu, acc[e], o);
    }
    if (lane == 0) {
        float m = acc[0]; int am = 0;
        #pragma unroll
        for (int e = 1; e < NE; e++) if (acc[e] > m) { m = acc[e]; am = e; }
        float pe[NE]; float s = 0.f;
        #pragma unroll
        for (int e = 0; e < NE; e++) { pe[e] = expf(acc[e] - m); s += pe[e]; }
        float inv = 1.0f / s;
        #pragma unroll
        for (int e = 0; e < NE; e++) g_probs[warp*NE + e] = pe[e] * inv;
        float lse = logf(s) + m;
        g_lse2[warp]    = lse * lse;
        g_expidx[warp]  = am;
        g_expprob[warp] = pe[am] * inv;
    }
}

// ---------------- stable ranks via packed prefix scan (1 block) -------------
__global__ void rank_kernel()
{
    __shared__ unsigned long long h0[1024], h1[1024];
    __shared__ int stotal[NE], sstart[NE];
    int t = threadIdx.x;
    int base = t * 8;
    int e_arr[8];
    int cnt[NE] = {0,0,0,0,0,0,0,0};
    #pragma unroll
    for (int i = 0; i < 8; i++) { int e = g_expidx[base+i]; e_arr[i] = e; cnt[e]++; }
    unsigned long long p0 = 0, p1 = 0;
    #pragma unroll
    for (int e = 0; e < 4; e++) {
        p0 |= (unsigned long long)cnt[e]   << (16*e);
        p1 |= (unsigned long long)cnt[e+4] << (16*e);
    }
    h0[t] = p0; h1[t] = p1;
    __syncthreads();
    for (int off = 1; off < 1024; off <<= 1) {
        unsigned long long v0 = (t >= off) ? h0[t-off] : 0ULL;
        unsigned long long v1 = (t >= off) ? h1[t-off] : 0ULL;
        __syncthreads();
        h0[t] += v0; h1[t] += v1;
        __syncthreads();
    }
    unsigned long long inc0 = h0[t], inc1 = h1[t];
    if (t == 1023) {
        #pragma unroll
        for (int e = 0; e < 4; e++) {
            stotal[e]   = (int)((inc0 >> (16*e)) & 0xFFFF);
            stotal[e+4] = (int)((inc1 >> (16*e)) & 0xFFFF);
        }
    }
    for (int i = t; i < MT; i += 1024) g_tok_of_slot[i] = -1;
    __syncthreads();
    if (t == 0) { int s = 0; for (int e = 0; e < NE; e++) { sstart[e] = s; s += stotal[e]; } }
    if (t < NE) g_counts[t] = stotal[t];
    __syncthreads();
    int loc[NE];
    #pragma unroll
    for (int e = 0; e < 4; e++) {
        loc[e]   = (int)((inc0 >> (16*e)) & 0xFFFF) - cnt[e];
        loc[e+4] = (int)((inc1 >> (16*e)) & 0xFFFF) - cnt[e+4];
    }
    #pragma unroll
    for (int i = 0; i < 8; i++) {
        int n = base + i, e = e_arr[i];
        int r = loc[e]++;
        g_rank[n] = r;
        g_sorted_tok[sstart[e] + r] = n;
        if (r < CAP) g_tok_of_slot[e*CAP + r] = n;
    }
}

// ------------- gather tokens -> fp16 expert buffers ------------------------
__global__ void gather_kernel(const float* __restrict__ x, float* __restrict__ out)
{
    int n = blockIdx.x;
    int t = threadIdx.x;   // 256
    int e = g_expidx[n];
    int r = g_rank[n];
    if (t == 0) g_scale[n] = g_expprob[g_sorted_tok[n]];
    if (r < CAP) {
        size_t base = ((size_t)(e*CAP + r)) * ND + t*4;
        float4 v = ((const float4*)(x + (size_t)n * ND))[t];
        __half2 a = __floats2half2_rn(v.x, v.y);
        __half2 b = __floats2half2_rn(v.z, v.w);
        uint2 pk;
        pk.x = *(uint32_t*)&a;
        pk.y = *(uint32_t*)&b;
        *(uint2*)(g_xh + base) = pk;
    } else {
        float4 z = make_float4(0.f, 0.f, 0.f, 0.f);
        ((float4*)(out + (size_t)n * ND))[t] = z;
    }
}

// ------------- weight transpose + fp16 convert: [E][K][N] -> [E][N][K] -----
template<int K, int N>
__global__ void wconv_kernel(const float* __restrict__ W,
                             __half* __restrict__ Wh)
{
    __shared__ float tile[32][33];
    int e = blockIdx.z;
    int n0 = blockIdx.x * 32, k0 = blockIdx.y * 32;
    const float* We = W + (size_t)e * K * N;
    int tx = threadIdx.x, ty = threadIdx.y;   // (32, 8)
    #pragma unroll
    for (int i = 0; i < 4; i++) {
        int k = k0 + ty + i*8;
        tile[ty + i*8][tx] = We[(size_t)k * N + n0 + tx];
    }
    __syncthreads();
    __half* Whe = Wh + (size_t)e * K * N;
    #pragma unroll
    for (int i = 0; i < 4; i++) {
        int n = n0 + ty + i*8;
        Whe[(size_t)n * K + k0 + tx] = __float2half(tile[tx][ty + i*8]);
    }
}

// ================== mma.sync fp16 single-pass grouped GEMM =================
__device__ __forceinline__ float gelu_exact(float v) {
    return 0.5f * v * (1.0f + erff(v * 0.70710678118654752f));
}

#define CP_ASYNC16(dst, src) \
    asm volatile("cp.async.cg.shared.global [%0], [%1], 16;" :: "r"(dst), "l"(src))
#define CP_COMMIT() asm volatile("cp.async.commit_group;" ::: "memory")
#define CP_WAIT1()  asm volatile("cp.async.wait_group 1;" ::: "memory")
#define CP_WAIT0()  asm volatile("cp.async.wait_group 0;" ::: "memory")

__device__ __forceinline__ void ldsm4(uint32_t* r, uint32_t addr) {
    asm volatile("ldmatrix.sync.aligned.m8n8.x4.shared.b16 {%0,%1,%2,%3}, [%4];"
                 : "=r"(r[0]), "=r"(r[1]), "=r"(r[2]), "=r"(r[3]) : "r"(addr));
}
__device__ __forceinline__ void mma16816(float* d, const uint32_t* a, const uint32_t* b) {
    asm volatile(
        "mma.sync.aligned.m16n8k16.row.col.f32.f16.f16.f32 "
        "{%0,%1,%2,%3}, {%4,%5,%6,%7}, {%8,%9}, {%0,%1,%2,%3};"
        : "+f"(d[0]), "+f"(d[1]), "+f"(d[2]), "+f"(d[3])
        : "r"(a[0]), "r"(a[1]), "r"(a[2]), "r"(a[3]), "r"(b[0]), "r"(b[1]));
}

// SMEM: 3 stages x 2 matrices (A, B), each 128 rows x 80B pitch
// (32 fp16 data = 64B + 16B pad -> conflict-free ldmatrix).
#define PITCH 80
#define MATB  (128 * PITCH)        // 10240
#define STAGEB (2 * MATB)          // 20480
#define GSMEM (3 * STAGEB)         // 61440

template<int KTOT, int NTOT, bool PHASE2>
__global__ __launch_bounds__(256, 2)
void tgemm_kernel(const __half* __restrict__ A_g,
                  const __half* __restrict__ B_g,
                  const float* __restrict__ bias,
                  float* __restrict__ outp)
{
    extern __shared__ char smem[];
    uint32_t sbase = smem_u32(smem);
    int tid = threadIdx.x;
    int wid = tid >> 5, lane = tid & 31;
    int wm = wid & 3, wn = wid >> 2;          // warp grid 4(M) x 2(N)
    int bn = blockIdx.x, bm = blockIdx.y;
    int e = bm >> 3;                          // 8 M-blocks per expert

    const __half* Ae = A_g + (size_t)bm * 128 * KTOT;
    const __half* Be = B_g + (size_t)e * NTOT * KTOT + (size_t)bn * 128 * KTOT;

    float acc[2][8][4];
    #pragma unroll
    for (int i = 0; i < 2; i++)
        #pragma unroll
        for (int j = 0; j < 8; j++)
            #pragma unroll
            for (int c = 0; c < 4; c++) acc[i][j][c] = 0.f;

    const int S = KTOT / 32;

    int r0 = tid >> 2, c0 = tid & 3;          // rows 0..63, 16B chunks

    auto load_stage = [&](int s, int buf) {
        int k0 = s * 32;
        uint32_t sb = sbase + buf * STAGEB;
        const __half* gA = Ae + (size_t)r0 * KTOT + k0 + c0 * 8;
        const __half* gB = Be + (size_t)r0 * KTOT + k0 + c0 * 8;
        uint32_t so = r0 * PITCH + c0 * 16;
        CP_ASYNC16(sb + so,          gA);
        CP_ASYNC16(sb + MATB + so,   gB);
        size_t gstep = (size_t)64 * KTOT;
        uint32_t sstep = 64 * PITCH;
        CP_ASYNC16(sb + so + sstep,        gA + gstep);
        CP_ASYNC16(sb + MATB + so + sstep, gB + gstep);
        CP_COMMIT();
    };

    // ldmatrix lane decomposition
    int lr = lane & 7, lq = (lane >> 3) & 1, lh = lane >> 4;

    load_stage(0, 0);
    load_stage(1, 1);
    for (int s = 0; s < S; s++) {
        int buf = s - (s/3)*3;                // s % 3
        if (s + 2 < S) {
            CP_WAIT1();
            __syncthreads();
            int nb = s + 2; nb = nb - (nb/3)*3;
            load_stage(s + 2, nb);
        } else {
            CP_WAIT0();
            __syncthreads();
        }

        uint32_t sb = sbase + buf * STAGEB;
        #pragma unroll
        for (int kk = 0; kk < 2; kk++) {
            uint32_t ah[2][4], bh[8][2];
            #pragma unroll
            for (int mi = 0; mi < 2; mi++) {
                int row = wm*32 + mi*16 + lr + lq*8;
                uint32_t off = row * PITCH + kk*32 + lh*16;
                ldsm4(ah[mi], sb + off);
            }
            #pragma unroll
            for (int nj2 = 0; nj2 < 4; nj2++) {
                int row = wn*64 + nj2*16 + lr + lh*8;
                uint32_t off = row * PITCH + kk*32 + lq*16;
                uint32_t t[4];
                ldsm4(t, sb + MATB + off);
                bh[2*nj2][0] = t[0]; bh[2*nj2][1] = t[1];
                bh[2*nj2+1][0] = t[2]; bh[2*nj2+1][1] = t[3];
            }
            #pragma unroll
            for (int mi = 0; mi < 2; mi++)
                #pragma unroll
                for (int nj = 0; nj < 8; nj++)
                    mma16816(acc[mi][nj], ah[mi], bh[nj]);
        }
        __syncthreads();
    }

    // ---------------- epilogue --------------------------------------------
    int qr = lane >> 2, qc = lane & 3;
    float2 bv[8];
    #pragma unroll
    for (int nj = 0; nj < 8; nj++) {
        int colg = bn*128 + wn*64 + nj*8 + 2*qc;
        bv[nj] = *(const float2*)(bias + (size_t)e * NTOT + colg);
    }
    if (!PHASE2) {
        #pragma unroll
        for (int mi = 0; mi < 2; mi++)
            #pragma unroll
            for (int h = 0; h < 2; h++) {
                int rowg = bm*128 + wm*32 + mi*16 + qr + h*8;
                #pragma unroll
                for (int nj = 0; nj < 8; nj++) {
                    int colg = bn*128 + wn*64 + nj*8 + 2*qc;
                    float v0 = acc[mi][nj][2*h]   + bv[nj].x;
                    float v1 = acc[mi][nj][2*h+1] + bv[nj].y;
                    __half2 hv = __floats2half2_rn(gelu_exact(v0), gelu_exact(v1));
                    *(__half2*)(g_hh + (size_t)rowg * NTOT + colg) = hv;
                }
            }
    } else {
        #pragma unroll
        for (int mi = 0; mi < 2; mi++)
            #pragma unroll
            for (int h = 0; h < 2; h++) {
                int slot = bm*128 + wm*32 + mi*16 + qr + h*8;
                int tok = g_tok_of_slot[slot];
                if (tok >= 0) {
                    float sc = g_scale[tok];
                    float* orow = outp + (size_t)tok * NTOT;
                    #pragma unroll
                    for (int nj = 0; nj < 8; nj++) {
                        int colg = bn*128 + wn*64 + nj*8 + 2*qc;
                        float2 ov;
                        ov.x = (acc[mi][nj][2*h]   + bv[nj].x) * sc;
                        ov.y = (acc[mi][nj][2*h+1] + bv[nj].y) * sc;
                        *(float2*)(orow + colg) = ov;
                    }
                }
            }
    }
}

// ---------------- aux loss (deterministic reduction, 1 block) ---------------
__global__ void aux_kernel(float* __restrict__ out_aux)
{
    __shared__ float sh[256];
    int t = threadIdx.x;
    float ls = 0.f;
    for (int n = t; n < NTOK; n += 256) ls += g_lse2[n];
    float ps[NE] = {0,0,0,0,0,0,0,0};
    for (int n = t; n < NTOK; n += 256) {
        #pragma unroll
        for (int e = 0; e < NE; e++) ps[e] += g_probs[n*NE + e];
    }
    __shared__ float red[NE + 1];
    sh[t] = ls; __syncthreads();
    for (int o = 128; o > 0; o >>= 1) { if (t < o) sh[t] += sh[t + o]; __syncthreads(); }
    if (t == 0) red[NE] = sh[0];
    __syncthreads();
    for (int e = 0; e < NE; e++) {
        sh[t] = ps[e]; __syncthreads();
        for (int o = 128; o > 0; o >>= 1) { if (t < o) sh[t] += sh[t + o]; __syncthreads(); }
        if (t == 0) red[e] = sh[0];
        __syncthreads();
    }
    if (t == 0) {
        float invN = 1.0f / (float)NTOK;
        float fb = 0.f;
        for (int e = 0; e < NE; e++) {
            float f_i = (float)g_counts[e] * invN;
            float p_i = red[e] * invN;
            fb += f_i * p_i;
        }
        float z = red[NE] * invN;
        out_aux[0] = 0.01f * (float)NE * fb + 0.001f * z;
    }
}

// ---------------------------------------------------------------------------
extern "C" void kernel_launch(void* const* d_in, const int* in_sizes, int n_in,
                              void* d_out, int out_size)
{
    const float* x  = (const float*)d_in[0];
    const float* Wg = (const float*)d_in[1];
    const float* W1 = (const float*)d_in[2];
    const float* b1 = (const float*)d_in[3];
    const float* W2 = (const float*)d_in[4];
    const float* b2 = (const float*)d_in[5];
    float* out = (float*)d_out;

    cudaFuncSetAttribute(tgemm_kernel<ND, NH, false>,
                         cudaFuncAttributeMaxDynamicSharedMemorySize, GSMEM);
    cudaFuncSetAttribute(tgemm_kernel<NH, ND, true>,
                         cudaFuncAttributeMaxDynamicSharedMemorySize, GSMEM);

    __half *xh, *hh, *w1h, *w2h;
    cudaGetSymbolAddress((void**)&xh,  g_xh);
    cudaGetSymbolAddress((void**)&hh,  g_hh);
    cudaGetSymbolAddress((void**)&w1h, g_w1h);
    cudaGetSymbolAddress((void**)&w2h, g_w2h);

    router_kernel<<<NTOK/8, 256>>>(x, Wg);
    rank_kernel<<<1, 1024>>>();
    gather_kernel<<<NTOK, 256>>>(x, out);

    // weight transpose + fp16 convert
    wconv_kernel<ND, NH><<<dim3(NH/32, ND/32, NE), dim3(32, 8)>>>(W1, w1h);
    wconv_kernel<NH, ND><<<dim3(ND/32, NH/32, NE), dim3(32, 8)>>>(W2, w2h);

    // GEMM1: [MT,ND] @ W1t -> gelu -> hidden (fp16)
    tgemm_kernel<ND, NH, false><<<dim3(NH/128, MT/128), 256, GSMEM>>>(
        xh, w1h, b1, out);
    // GEMM2: [MT,NH] @ W2t -> bias + scale -> scatter to out
    tgemm_kernel<NH, ND, true><<<dim3(ND/128, MT/128), 256, GSMEM>>>(
        hh, w2h, b2, out);

    if (out_size > NTOK * ND) {
        aux_kernel<<<1, 256>>>(out + (size_t)NTOK * ND);
    }
}

// round 9
// speedup vs baseline: 5.6938x; 1.0671x over previous
#include <cuda_runtime.h>
#include <cuda_fp16.h>
#include <math.h>
#include <stdint.h>

// Problem constants (fixed for MixtureOfExperts_498216206779)
#define NB 4
#define NT 2048
#define ND 1024
#define NH 4096
#define NE 8
#define NTOK (NB*NT)          // 8192
#define CAP 1024
#define MT (NE*CAP)           // 8192

// ---------------- scratch (device globals; no allocation allowed) ----------
__device__ float g_probs[NTOK*NE];
__device__ float g_lse2[NTOK];
__device__ int   g_expidx[NTOK];
__device__ float g_expprob[NTOK];
__device__ int   g_rank[NTOK];
__device__ int   g_sorted_tok[NTOK];
__device__ int   g_counts[NE];
__device__ int   g_tok_of_slot[MT];
__device__ float g_scale[NTOK];
// fp16 buffers (single precision pass; error budget ~4.2e-4 < 1e-3)
__device__ __half g_xh[(size_t)MT*ND];      // tokens [M][K]
__device__ __half g_hh[(size_t)MT*NH];      // hidden [M][K]
__device__ __half g_w1h[(size_t)NE*ND*NH];  // [E][N=NH][K=ND]
__device__ __half g_w2h[(size_t)NE*NH*ND];  // [E][N=ND][K=NH]

__device__ __forceinline__ uint32_t smem_u32(const void* p) {
    return (uint32_t)__cvta_generic_to_shared((void*)p);
}

// ---------------- router: logits, softmax, argmax, lse^2 -------------------
__global__ void router_kernel(const float* __restrict__ x,
                              const float* __restrict__ Wg)
{
    int warp = (blockIdx.x * blockDim.x + threadIdx.x) >> 5;
    int lane = threadIdx.x & 31;
    if (warp >= NTOK) return;
    const float* xr = x + (size_t)warp * ND;
    float acc[NE] = {0,0,0,0,0,0,0,0};
    for (int d = lane; d < ND; d += 32) {
        float xv = xr[d];
        const float* wr = Wg + d * NE;
        #pragma unroll
        for (int e = 0; e < NE; e++) acc[e] += xv * wr[e];
    }
    #pragma unroll
    for (int e = 0; e < NE; e++) {
        #pragma unroll
        for (int o = 16; o > 0; o >>= 1)
            acc[e] += __shfl_xor_sync(0xFFFFFFFFu, acc[e], o);
    }
    if (lane == 0) {
        float m = acc[0]; int am = 0;
        #pragma unroll
        for (int e = 1; e < NE; e++) if (acc[e] > m) { m = acc[e]; am = e; }
        float pe[NE]; float s = 0.f;
        #pragma unroll
        for (int e = 0; e < NE; e++) { pe[e] = expf(acc[e] - m); s += pe[e]; }
        float inv = 1.0f / s;
        #pragma unroll
        for (int e = 0; e < NE; e++) g_probs[warp*NE + e] = pe[e] * inv;
        float lse = logf(s) + m;
        g_lse2[warp]    = lse * lse;
        g_expidx[warp]  = am;
        g_expprob[warp] = pe[am] * inv;
    }
}

// ---------------- stable ranks via packed prefix scan (1 block) -------------
__global__ void rank_kernel()
{
    __shared__ unsigned long long h0[1024], h1[1024];
    __shared__ int stotal[NE], sstart[NE];
    int t = threadIdx.x;
    int base = t * 8;
    int e_arr[8];
    int cnt[NE] = {0,0,0,0,0,0,0,0};
    #pragma unroll
    for (int i = 0; i < 8; i++) { int e = g_expidx[base+i]; e_arr[i] = e; cnt[e]++; }
    unsigned long long p0 = 0, p1 = 0;
    #pragma unroll
    for (int e = 0; e < 4; e++) {
        p0 |= (unsigned long long)cnt[e]   << (16*e);
        p1 |= (unsigned long long)cnt[e+4] << (16*e);
    }
    h0[t] = p0; h1[t] = p1;
    __syncthreads();
    for (int off = 1; off < 1024; off <<= 1) {
        unsigned long long v0 = (t >= off) ? h0[t-off] : 0ULL;
        unsigned long long v1 = (t >= off) ? h1[t-off] : 0ULL;
        __syncthreads();
        h0[t] += v0; h1[t] += v1;
        __syncthreads();
    }
    unsigned long long inc0 = h0[t], inc1 = h1[t];
    if (t == 1023) {
        #pragma unroll
        for (int e = 0; e < 4; e++) {
            stotal[e]   = (int)((inc0 >> (16*e)) & 0xFFFF);
            stotal[e+4] = (int)((inc1 >> (16*e)) & 0xFFFF);
        }
    }
    for (int i = t; i < MT; i += 1024) g_tok_of_slot[i] = -1;
    __syncthreads();
    if (t == 0) { int s = 0; for (int e = 0; e < NE; e++) { sstart[e] = s; s += stotal[e]; } }
    if (t < NE) g_counts[t] = stotal[t];
    __syncthreads();
    int loc[NE];
    #pragma unroll
    for (int e = 0; e < 4; e++) {
        loc[e]   = (int)((inc0 >> (16*e)) & 0xFFFF) - cnt[e];
        loc[e+4] = (int)((inc1 >> (16*e)) & 0xFFFF) - cnt[e+4];
    }
    #pragma unroll
    for (int i = 0; i < 8; i++) {
        int n = base + i, e = e_arr[i];
        int r = loc[e]++;
        g_rank[n] = r;
        g_sorted_tok[sstart[e] + r] = n;
        if (r < CAP) g_tok_of_slot[e*CAP + r] = n;
    }
}

// ------------- gather tokens -> fp16 expert buffers ------------------------
__global__ void gather_kernel(const float* __restrict__ x, float* __restrict__ out)
{
    int n = blockIdx.x;
    int t = threadIdx.x;   // 256
    int e = g_expidx[n];
    int r = g_rank[n];
    if (t == 0) g_scale[n] = g_expprob[g_sorted_tok[n]];
    if (r < CAP) {
        size_t base = ((size_t)(e*CAP + r)) * ND + t*4;
        float4 v = ((const float4*)(x + (size_t)n * ND))[t];
        __half2 a = __floats2half2_rn(v.x, v.y);
        __half2 b = __floats2half2_rn(v.z, v.w);
        uint2 pk;
        pk.x = *(uint32_t*)&a;
        pk.y = *(uint32_t*)&b;
        *(uint2*)(g_xh + base) = pk;
    } else {
        float4 z = make_float4(0.f, 0.f, 0.f, 0.f);
        ((float4*)(out + (size_t)n * ND))[t] = z;
    }
}

// ------------- weight transpose + fp16 convert: [E][K][N] -> [E][N][K] -----
template<int K, int N>
__global__ void wconv_kernel(const float* __restrict__ W,
                             __half* __restrict__ Wh)
{
    __shared__ float tile[32][33];
    int e = blockIdx.z;
    int n0 = blockIdx.x * 32, k0 = blockIdx.y * 32;
    const float* We = W + (size_t)e * K * N;
    int tx = threadIdx.x, ty = threadIdx.y;   // (32, 8)
    #pragma unroll
    for (int i = 0; i < 4; i++) {
        int k = k0 + ty + i*8;
        tile[ty + i*8][tx] = We[(size_t)k * N + n0 + tx];
    }
    __syncthreads();
    __half* Whe = Wh + (size_t)e * K * N;
    #pragma unroll
    for (int i = 0; i < 4; i++) {
        int n = n0 + ty + i*8;
        Whe[(size_t)n * K + k0 + tx] = __float2half(tile[tx][ty + i*8]);
    }
}

// ================== mma.sync fp16 single-pass grouped GEMM =================
// 128x128 block, 4 warps, 64x64 warp tile, 4-stage cp.async pipeline.
__device__ __forceinline__ float gelu_exact(float v) {
    return 0.5f * v * (1.0f + erff(v * 0.70710678118654752f));
}

#define CP_ASYNC16(dst, src) \
    asm volatile("cp.async.cg.shared.global [%0], [%1], 16;" :: "r"(dst), "l"(src))
#define CP_COMMIT() asm volatile("cp.async.commit_group;" ::: "memory")
#define CP_WAITG(n) asm volatile("cp.async.wait_group %0;" :: "n"(n) : "memory")

__device__ __forceinline__ void ldsm4(uint32_t* r, uint32_t addr) {
    asm volatile("ldmatrix.sync.aligned.m8n8.x4.shared.b16 {%0,%1,%2,%3}, [%4];"
                 : "=r"(r[0]), "=r"(r[1]), "=r"(r[2]), "=r"(r[3]) : "r"(addr));
}
__device__ __forceinline__ void mma16816(float* d, const uint32_t* a, const uint32_t* b) {
    asm volatile(
        "mma.sync.aligned.m16n8k16.row.col.f32.f16.f16.f32 "
        "{%0,%1,%2,%3}, {%4,%5,%6,%7}, {%8,%9}, {%0,%1,%2,%3};"
        : "+f"(d[0]), "+f"(d[1]), "+f"(d[2]), "+f"(d[3])
        : "r"(a[0]), "r"(a[1]), "r"(a[2]), "r"(a[3]), "r"(b[0]), "r"(b[1]));
}

// SMEM: 4 stages x 2 matrices (A, B), each 128 rows x 80B pitch
// (32 fp16 data = 64B + 16B pad -> conflict-free ldmatrix).
#define PITCH 80
#define MATB  (128 * PITCH)        // 10240
#define STAGEB (2 * MATB)          // 20480
#define GSMEM (4 * STAGEB)         // 81920

template<int KTOT, int NTOT, bool PHASE2>
__global__ __launch_bounds__(128, 2)
void tgemm_kernel(const __half* __restrict__ A_g,
                  const __half* __restrict__ B_g,
                  const float* __restrict__ bias,
                  float* __restrict__ outp)
{
    extern __shared__ char smem[];
    uint32_t sbase = smem_u32(smem);
    int tid = threadIdx.x;
    int wid = tid >> 5, lane = tid & 31;
    int wm = wid & 1, wn = wid >> 1;          // warp grid 2(M) x 2(N), 64x64 tiles
    int bn = blockIdx.x, bm = blockIdx.y;
    int e = bm >> 3;                          // 8 M-blocks per expert

    const __half* Ae = A_g + (size_t)bm * 128 * KTOT;
    const __half* Be = B_g + (size_t)e * NTOT * KTOT + (size_t)bn * 128 * KTOT;

    float acc[4][8][4];
    #pragma unroll
    for (int i = 0; i < 4; i++)
        #pragma unroll
        for (int j = 0; j < 8; j++)
            #pragma unroll
            for (int c = 0; c < 4; c++) acc[i][j][c] = 0.f;

    const int S = KTOT / 32;

    int r0 = tid >> 2, c0 = tid & 3;          // rows 0..31 base, 16B chunks

    auto load_stage = [&](int s, int buf) {
        int k0 = s * 32;
        uint32_t sb = sbase + buf * STAGEB;
        const __half* gA = Ae + (size_t)r0 * KTOT + k0 + c0 * 8;
        const __half* gB = Be + (size_t)r0 * KTOT + k0 + c0 * 8;
        uint32_t so = r0 * PITCH + c0 * 16;
        #pragma unroll
        for (int i = 0; i < 4; i++) {
            size_t gstep = (size_t)(i * 32) * KTOT;
            uint32_t sstep = (i * 32) * PITCH;
            CP_ASYNC16(sb + so + sstep,        gA + gstep);
            CP_ASYNC16(sb + MATB + so + sstep, gB + gstep);
        }
        CP_COMMIT();
    };

    // ldmatrix lane decomposition
    int lr = lane & 7, lq = (lane >> 3) & 1, lh = lane >> 4;

    load_stage(0, 0);
    load_stage(1, 1);
    load_stage(2, 2);
    for (int s = 0; s < S; s++) {
        int buf = s & 3;
        if (s + 3 < S) {
            load_stage(s + 3, (s + 3) & 3);
            CP_WAITG(3);
        } else {
            int rem = S - 1 - s;
            if (rem == 2)      CP_WAITG(2);
            else if (rem == 1) CP_WAITG(1);
            else               CP_WAITG(0);
        }
        __syncthreads();

        uint32_t sb = sbase + buf * STAGEB;
        #pragma unroll
        for (int kk = 0; kk < 2; kk++) {
            uint32_t ah[4][4], bh[8][2];
            #pragma unroll
            for (int mi2 = 0; mi2 < 2; mi2++) {
                // ldmatrix x4 covers 16 rows x 16 cols; do 4 for 64 rows
                int row = wm*64 + mi2*32 + lr + lq*8;
                uint32_t off = row * PITCH + kk*32 + lh*16;
                ldsm4(ah[2*mi2], sb + off);
                int row2 = row + 16;
                uint32_t off2 = row2 * PITCH + kk*32 + lh*16;
                ldsm4(ah[2*mi2+1], sb + off2);
            }
            #pragma unroll
            for (int nj2 = 0; nj2 < 4; nj2++) {
                int row = wn*64 + nj2*16 + lr + lh*8;
                uint32_t off = row * PITCH + kk*32 + lq*16;
                uint32_t t[4];
                ldsm4(t, sb + MATB + off);
                bh[2*nj2][0] = t[0]; bh[2*nj2][1] = t[1];
                bh[2*nj2+1][0] = t[2]; bh[2*nj2+1][1] = t[3];
            }
            #pragma unroll
            for (int mi = 0; mi < 4; mi++)
                #pragma unroll
                for (int nj = 0; nj < 8; nj++)
                    mma16816(acc[mi][nj], ah[mi], bh[nj]);
        }
        __syncthreads();
    }

    // ---------------- epilogue --------------------------------------------
    int qr = lane >> 2, qc = lane & 3;
    float2 bv[8];
    #pragma unroll
    for (int nj = 0; nj < 8; nj++) {
        int colg = bn*128 + wn*64 + nj*8 + 2*qc;
        bv[nj] = *(const float2*)(bias + (size_t)e * NTOT + colg);
    }
    if (!PHASE2) {
        #pragma unroll
        for (int mi = 0; mi < 4; mi++)
            #pragma unroll
            for (int h = 0; h < 2; h++) {
                int rowg = bm*128 + wm*64 + mi*16 + qr + h*8;
                #pragma unroll
                for (int nj = 0; nj < 8; nj++) {
                    int colg = bn*128 + wn*64 + nj*8 + 2*qc;
                    float v0 = acc[mi][nj][2*h]   + bv[nj].x;
                    float v1 = acc[mi][nj][2*h+1] + bv[nj].y;
                    __half2 hv = __floats2half2_rn(gelu_exact(v0), gelu_exact(v1));
                    *(__half2*)(g_hh + (size_t)rowg * NTOT + colg) = hv;
                }
            }
    } else {
        #pragma unroll
        for (int mi = 0; mi < 4; mi++)
            #pragma unroll
            for (int h = 0; h < 2; h++) {
                int slot = bm*128 + wm*64 + mi*16 + qr + h*8;
                int tok = g_tok_of_slot[slot];
                if (tok >= 0) {
                    float sc = g_scale[tok];
                    float* orow = outp + (size_t)tok * NTOT;
                    #pragma unroll
                    for (int nj = 0; nj < 8; nj++) {
                        int colg = bn*128 + wn*64 + nj*8 + 2*qc;
                        float2 ov;
                        ov.x = (acc[mi][nj][2*h]   + bv[nj].x) * sc;
                        ov.y = (acc[mi][nj][2*h+1] + bv[nj].y) * sc;
                        *(float2*)(orow + colg) = ov;
                    }
                }
            }
    }
}

// ---------------- aux loss (deterministic reduction, 1 block) ---------------
__global__ void aux_kernel(float* __restrict__ out_aux)
{
    __shared__ float sh[256];
    int t = threadIdx.x;
    float ls = 0.f;
    for (int n = t; n < NTOK; n += 256) ls += g_lse2[n];
    float ps[NE] = {0,0,0,0,0,0,0,0};
    for (int n = t; n < NTOK; n += 256) {
        #pragma unroll
        for (int e = 0; e < NE; e++) ps[e] += g_probs[n*NE + e];
    }
    __shared__ float red[NE + 1];
    sh[t] = ls; __syncthreads();
    for (int o = 128; o > 0; o >>= 1) { if (t < o) sh[t] += sh[t + o]; __syncthreads(); }
    if (t == 0) red[NE] = sh[0];
    __syncthreads();
    for (int e = 0; e < NE; e++) {
        sh[t] = ps[e]; __syncthreads();
        for (int o = 128; o > 0; o >>= 1) { if (t < o) sh[t] += sh[t + o]; __syncthreads(); }
        if (t == 0) red[e] = sh[0];
        __syncthreads();
    }
    if (t == 0) {
        float invN = 1.0f / (float)NTOK;
        float fb = 0.f;
        for (int e = 0; e < NE; e++) {
            float f_i = (float)g_counts[e] * invN;
            float p_i = red[e] * invN;
            fb += f_i * p_i;
        }
        float z = red[NE] * invN;
        out_aux[0] = 0.01f * (float)NE * fb + 0.001f * z;
    }
}

// ---------------------------------------------------------------------------
extern "C" void kernel_launch(void* const* d_in, const int* in_sizes, int n_in,
                              void* d_out, int out_size)
{
    const float* x  = (const float*)d_in[0];
    const float* Wg = (const float*)d_in[1];
    const float* W1 = (const float*)d_in[2];
    const float* b1 = (const float*)d_in[3];
    const float* W2 = (const float*)d_in[4];
    const float* b2 = (const float*)d_in[5];
    float* out = (float*)d_out;

    cudaFuncSetAttribute(tgemm_kernel<ND, NH, false>,
                         cudaFuncAttributeMaxDynamicSharedMemorySize, GSMEM);
    cudaFuncSetAttribute(tgemm_kernel<NH, ND, true>,
                         cudaFuncAttributeMaxDynamicSharedMemorySize, GSMEM);

    __half *xh, *hh, *w1h, *w2h;
    cudaGetSymbolAddress((void**)&xh,  g_xh);
    cudaGetSymbolAddress((void**)&hh,  g_hh);
    cudaGetSymbolAddress((void**)&w1h, g_w1h);
    cudaGetSymbolAddress((void**)&w2h, g_w2h);

    router_kernel<<<NTOK/8, 256>>>(x, Wg);
    rank_kernel<<<1, 1024>>>();
    gather_kernel<<<NTOK, 256>>>(x, out);

    // weight transpose + fp16 convert
    wconv_kernel<ND, NH><<<dim3(NH/32, ND/32, NE), dim3(32, 8)>>>(W1, w1h);
    wconv_kernel<NH, ND><<<dim3(ND/32, NH/32, NE), dim3(32, 8)>>>(W2, w2h);

    // GEMM1: [MT,ND] @ W1t -> gelu -> hidden (fp16)
    tgemm_kernel<ND, NH, false><<<dim3(NH/128, MT/128), 128, GSMEM>>>(
        xh, w1h, b1, out);
    // GEMM2: [MT,NH] @ W2t -> bias + scale -> scatter to out
    tgemm_kernel<NH, ND, true><<<dim3(ND/128, MT/128), 128, GSMEM>>>(
        hh, w2h, b2, out);

    if (out_size > NTOK * ND) {
        aux_kernel<<<1, 256>>>(out + (size_t)NTOK * ND);
    }
}

// round 10
// speedup vs baseline: 5.8545x; 1.0282x over previous
#include <cuda_runtime.h>
#include <cuda_fp16.h>
#include <math.h>
#include <stdint.h>

// Problem constants (fixed for MixtureOfExperts_498216206779)
#define NB 4
#define NT 2048
#define ND 1024
#define NH 4096
#define NE 8
#define NTOK (NB*NT)          // 8192
#define CAP 1024
#define MT (NE*CAP)           // 8192

// ---------------- scratch (device globals; no allocation allowed) ----------
__device__ float g_probs[NTOK*NE];
__device__ float g_lse2[NTOK];
__device__ int   g_expidx[NTOK];
__device__ float g_expprob[NTOK];
__device__ int   g_rank[NTOK];
__device__ int   g_sorted_tok[NTOK];
__device__ int   g_counts[NE];
__device__ int   g_tok_of_slot[MT];
__device__ float g_scale[NTOK];
// fp16 buffers (single precision pass; error budget ~4.2e-4 < 1e-3)
__device__ __half g_xh[(size_t)MT*ND];      // tokens [M][K]
__device__ __half g_hh[(size_t)MT*NH];      // hidden [M][K]
__device__ __half g_w1h[(size_t)NE*ND*NH];  // [E][N=NH][K=ND]
__device__ __half g_w2h[(size_t)NE*NH*ND];  // [E][N=ND][K=NH]

__device__ __forceinline__ uint32_t smem_u32(const void* p) {
    return (uint32_t)__cvta_generic_to_shared((void*)p);
}

// ------------- weight transpose + fp16 convert: [E][K][N] -> [E][N][K] -----
// Tile: TK=64 x TN=32.  Writes are __half2 -> 128B fully-coalesced rows.
template<int K, int N>
__global__ void wconv_kernel(const float* __restrict__ W,
                             __half* __restrict__ Wh)
{
    __shared__ float tile[64][33];
    int e = blockIdx.z;
    int n0 = blockIdx.x * 32, k0 = blockIdx.y * 64;
    const float* We = W + (size_t)e * K * N;
    int tx = threadIdx.x, ty = threadIdx.y;   // (32, 8)
    #pragma unroll
    for (int i = 0; i < 8; i++) {
        int k = k0 + ty + i*8;
        tile[ty + i*8][tx] = We[(size_t)k * N + n0 + tx];
    }
    __syncthreads();
    __half* Whe = Wh + (size_t)e * K * N;
    #pragma unroll
    for (int i = 0; i < 4; i++) {
        int n = n0 + ty + i*8;
        float a = tile[2*tx][ty + i*8];
        float b = tile[2*tx+1][ty + i*8];
        *(__half2*)(Whe + (size_t)n * K + k0 + 2*tx) = __floats2half2_rn(a, b);
    }
}

// ---------------- router: logits, softmax, argmax, lse^2 -------------------
__global__ void router_kernel(const float* __restrict__ x,
                              const float* __restrict__ Wg)
{
    int warp = (blockIdx.x * blockDim.x + threadIdx.x) >> 5;
    int lane = threadIdx.x & 31;
    if (warp >= NTOK) return;
    const float* xr = x + (size_t)warp * ND;
    float acc[NE] = {0,0,0,0,0,0,0,0};
    for (int d = lane; d < ND; d += 32) {
        float xv = xr[d];
        const float* wr = Wg + d * NE;
        #pragma unroll
        for (int e = 0; e < NE; e++) acc[e] += xv * wr[e];
    }
    #pragma unroll
    for (int e = 0; e < NE; e++) {
        #pragma unroll
        for (int o = 16; o > 0; o >>= 1)
            acc[e] += __shfl_xor_sync(0xFFFFFFFFu, acc[e], o);
    }
    if (lane == 0) {
        float m = acc[0]; int am = 0;
        #pragma unroll
        for (int e = 1; e < NE; e++) if (acc[e] > m) { m = acc[e]; am = e; }
        float pe[NE]; float s = 0.f;
        #pragma unroll
        for (int e = 0; e < NE; e++) { pe[e] = expf(acc[e] - m); s += pe[e]; }
        float inv = 1.0f / s;
        #pragma unroll
        for (int e = 0; e < NE; e++) g_probs[warp*NE + e] = pe[e] * inv;
        float lse = logf(s) + m;
        g_lse2[warp]    = lse * lse;
        g_expidx[warp]  = am;
        g_expprob[warp] = pe[am] * inv;
    }
}

// ---------------- stable ranks via packed prefix scan (1 block) -------------
__global__ void rank_kernel()
{
    __shared__ unsigned long long h0[1024], h1[1024];
    __shared__ int stotal[NE], sstart[NE];
    int t = threadIdx.x;
    int base = t * 8;
    int e_arr[8];
    int cnt[NE] = {0,0,0,0,0,0,0,0};
    #pragma unroll
    for (int i = 0; i < 8; i++) { int e = g_expidx[base+i]; e_arr[i] = e; cnt[e]++; }
    unsigned long long p0 = 0, p1 = 0;
    #pragma unroll
    for (int e = 0; e < 4; e++) {
        p0 |= (unsigned long long)cnt[e]   << (16*e);
        p1 |= (unsigned long long)cnt[e+4] << (16*e);
    }
    h0[t] = p0; h1[t] = p1;
    __syncthreads();
    for (int off = 1; off < 1024; off <<= 1) {
        unsigned long long v0 = (t >= off) ? h0[t-off] : 0ULL;
        unsigned long long v1 = (t >= off) ? h1[t-off] : 0ULL;
        __syncthreads();
        h0[t] += v0; h1[t] += v1;
        __syncthreads();
    }
    unsigned long long inc0 = h0[t], inc1 = h1[t];
    if (t == 1023) {
        #pragma unroll
        for (int e = 0; e < 4; e++) {
            stotal[e]   = (int)((inc0 >> (16*e)) & 0xFFFF);
            stotal[e+4] = (int)((inc1 >> (16*e)) & 0xFFFF);
        }
    }
    for (int i = t; i < MT; i += 1024) g_tok_of_slot[i] = -1;
    __syncthreads();
    if (t == 0) { int s = 0; for (int e = 0; e < NE; e++) { sstart[e] = s; s += stotal[e]; } }
    if (t < NE) g_counts[t] = stotal[t];
    __syncthreads();
    int loc[NE];
    #pragma unroll
    for (int e = 0; e < 4; e++) {
        loc[e]   = (int)((inc0 >> (16*e)) & 0xFFFF) - cnt[e];
        loc[e+4] = (int)((inc1 >> (16*e)) & 0xFFFF) - cnt[e+4];
    }
    #pragma unroll
    for (int i = 0; i < 8; i++) {
        int n = base + i, e = e_arr[i];
        int r = loc[e]++;
        g_rank[n] = r;
        g_sorted_tok[sstart[e] + r] = n;
        if (r < CAP) g_tok_of_slot[e*CAP + r] = n;
    }
}

// ------------- gather tokens -> fp16 expert buffers ------------------------
__global__ void gather_kernel(const float* __restrict__ x, float* __restrict__ out)
{
    int n = blockIdx.x;
    int t = threadIdx.x;   // 256
    int e = g_expidx[n];
    int r = g_rank[n];
    if (t == 0) g_scale[n] = g_expprob[g_sorted_tok[n]];
    if (r < CAP) {
        size_t base = ((size_t)(e*CAP + r)) * ND + t*4;
        float4 v = ((const float4*)(x + (size_t)n * ND))[t];
        __half2 a = __floats2half2_rn(v.x, v.y);
        __half2 b = __floats2half2_rn(v.z, v.w);
        uint2 pk;
        pk.x = *(uint32_t*)&a;
        pk.y = *(uint32_t*)&b;
        *(uint2*)(g_xh + base) = pk;
    } else {
        float4 z = make_float4(0.f, 0.f, 0.f, 0.f);
        ((float4*)(out + (size_t)n * ND))[t] = z;
    }
}

// ================== mma.sync fp16 single-pass grouped GEMM =================
// 128x128 block, 4 warps, 64x64 warp tile, 4-stage cp.async pipeline.
__device__ __forceinline__ float gelu_exact(float v) {
    return 0.5f * v * (1.0f + erff(v * 0.70710678118654752f));
}

#define CP_ASYNC16(dst, src) \
    asm volatile("cp.async.cg.shared.global [%0], [%1], 16;" :: "r"(dst), "l"(src))
#define CP_COMMIT() asm volatile("cp.async.commit_group;" ::: "memory")
#define CP_WAITG(n) asm volatile("cp.async.wait_group %0;" :: "n"(n) : "memory")

__device__ __forceinline__ void ldsm4(uint32_t* r, uint32_t addr) {
    asm volatile("ldmatrix.sync.aligned.m8n8.x4.shared.b16 {%0,%1,%2,%3}, [%4];"
                 : "=r"(r[0]), "=r"(r[1]), "=r"(r[2]), "=r"(r[3]) : "r"(addr));
}
__device__ __forceinline__ void mma16816(float* d, const uint32_t* a, const uint32_t* b) {
    asm volatile(
        "mma.sync.aligned.m16n8k16.row.col.f32.f16.f16.f32 "
        "{%0,%1,%2,%3}, {%4,%5,%6,%7}, {%8,%9}, {%0,%1,%2,%3};"
        : "+f"(d[0]), "+f"(d[1]), "+f"(d[2]), "+f"(d[3])
        : "r"(a[0]), "r"(a[1]), "r"(a[2]), "r"(a[3]), "r"(b[0]), "r"(b[1]));
}

// SMEM: 4 stages x 2 matrices (A, B), each 128 rows x 80B pitch
// (32 fp16 data = 64B + 16B pad -> conflict-free ldmatrix).
#define PITCH 80
#define MATB  (128 * PITCH)        // 10240
#define STAGEB (2 * MATB)          // 20480
#define GSMEM (4 * STAGEB)         // 81920

template<int KTOT, int NTOT, bool PHASE2>
__global__ __launch_bounds__(128, 2)
void tgemm_kernel(const __half* __restrict__ A_g,
                  const __half* __restrict__ B_g,
                  const float* __restrict__ bias,
                  float* __restrict__ outp)
{
    extern __shared__ char smem[];
    uint32_t sbase = smem_u32(smem);
    int tid = threadIdx.x;
    int wid = tid >> 5, lane = tid & 31;
    int wm = wid & 1, wn = wid >> 1;          // warp grid 2(M) x 2(N), 64x64 tiles
    int bn = blockIdx.x, bm = blockIdx.y;
    int e = bm >> 3;                          // 8 M-blocks per expert

    const __half* Ae = A_g + (size_t)bm * 128 * KTOT;
    const __half* Be = B_g + (size_t)e * NTOT * KTOT + (size_t)bn * 128 * KTOT;

    float acc[4][8][4];
    #pragma unroll
    for (int i = 0; i < 4; i++)
        #pragma unroll
        for (int j = 0; j < 8; j++)
            #pragma unroll
            for (int c = 0; c < 4; c++) acc[i][j][c] = 0.f;

    const int S = KTOT / 32;

    int r0 = tid >> 2, c0 = tid & 3;          // rows 0..31 base, 16B chunks

    auto load_stage = [&](int s, int buf) {
        int k0 = s * 32;
        uint32_t sb = sbase + buf * STAGEB;
        const __half* gA = Ae + (size_t)r0 * KTOT + k0 + c0 * 8;
        const __half* gB = Be + (size_t)r0 * KTOT + k0 + c0 * 8;
        uint32_t so = r0 * PITCH + c0 * 16;
        #pragma unroll
        for (int i = 0; i < 4; i++) {
            size_t gstep = (size_t)(i * 32) * KTOT;
            uint32_t sstep = (i * 32) * PITCH;
            CP_ASYNC16(sb + so + sstep,        gA + gstep);
            CP_ASYNC16(sb + MATB + so + sstep, gB + gstep);
        }
        CP_COMMIT();
    };

    // ldmatrix lane decomposition
    int lr = lane & 7, lq = (lane >> 3) & 1, lh = lane >> 4;

    load_stage(0, 0);
    load_stage(1, 1);
    load_stage(2, 2);
    for (int s = 0; s < S; s++) {
        int buf = s & 3;
        if (s + 3 < S) {
            load_stage(s + 3, (s + 3) & 3);
            CP_WAITG(3);
        } else {
            int rem = S - 1 - s;
            if (rem == 2)      CP_WAITG(2);
            else if (rem == 1) CP_WAITG(1);
            else               CP_WAITG(0);
        }
        __syncthreads();

        uint32_t sb = sbase + buf * STAGEB;
        #pragma unroll
        for (int kk = 0; kk < 2; kk++) {
            uint32_t ah[4][4], bh[8][2];
            #pragma unroll
            for (int mi2 = 0; mi2 < 2; mi2++) {
                int row = wm*64 + mi2*32 + lr + lq*8;
                uint32_t off = row * PITCH + kk*32 + lh*16;
                ldsm4(ah[2*mi2], sb + off);
                int row2 = row + 16;
                uint32_t off2 = row2 * PITCH + kk*32 + lh*16;
                ldsm4(ah[2*mi2+1], sb + off2);
            }
            #pragma unroll
            for (int nj2 = 0; nj2 < 4; nj2++) {
                int row = wn*64 + nj2*16 + lr + lh*8;
                uint32_t off = row * PITCH + kk*32 + lq*16;
                uint32_t t[4];
                ldsm4(t, sb + MATB + off);
                bh[2*nj2][0] = t[0]; bh[2*nj2][1] = t[1];
                bh[2*nj2+1][0] = t[2]; bh[2*nj2+1][1] = t[3];
            }
            #pragma unroll
            for (int mi = 0; mi < 4; mi++)
                #pragma unroll
                for (int nj = 0; nj < 8; nj++)
                    mma16816(acc[mi][nj], ah[mi], bh[nj]);
        }
        __syncthreads();
    }

    // ---------------- epilogue --------------------------------------------
    int qr = lane >> 2, qc = lane & 3;
    float2 bv[8];
    #pragma unroll
    for (int nj = 0; nj < 8; nj++) {
        int colg = bn*128 + wn*64 + nj*8 + 2*qc;
        bv[nj] = *(const float2*)(bias + (size_t)e * NTOT + colg);
    }
    if (!PHASE2) {
        #pragma unroll
        for (int mi = 0; mi < 4; mi++)
            #pragma unroll
            for (int h = 0; h < 2; h++) {
                int rowg = bm*128 + wm*64 + mi*16 + qr + h*8;
                #pragma unroll
                for (int nj = 0; nj < 8; nj++) {
                    int colg = bn*128 + wn*64 + nj*8 + 2*qc;
                    float v0 = acc[mi][nj][2*h]   + bv[nj].x;
                    float v1 = acc[mi][nj][2*h+1] + bv[nj].y;
                    __half2 hv = __floats2half2_rn(gelu_exact(v0), gelu_exact(v1));
                    *(__half2*)(g_hh + (size_t)rowg * NTOT + colg) = hv;
                }
            }
    } else {
        #pragma unroll
        for (int mi = 0; mi < 4; mi++)
            #pragma unroll
            for (int h = 0; h < 2; h++) {
                int slot = bm*128 + wm*64 + mi*16 + qr + h*8;
                int tok = g_tok_of_slot[slot];
                if (tok >= 0) {
                    float sc = g_scale[tok];
                    float* orow = outp + (size_t)tok * NTOT;
                    #pragma unroll
                    for (int nj = 0; nj < 8; nj++) {
                        int colg = bn*128 + wn*64 + nj*8 + 2*qc;
                        float2 ov;
                        ov.x = (acc[mi][nj][2*h]   + bv[nj].x) * sc;
                        ov.y = (acc[mi][nj][2*h+1] + bv[nj].y) * sc;
                        *(float2*)(orow + colg) = ov;
                    }
                }
            }
    }
}

// ---------------- aux loss (deterministic reduction, 1 block) ---------------
__global__ void aux_kernel(float* __restrict__ out_aux)
{
    __shared__ float sh[256];
    int t = threadIdx.x;
    float ls = 0.f;
    for (int n = t; n < NTOK; n += 256) ls += g_lse2[n];
    float ps[NE] = {0,0,0,0,0,0,0,0};
    for (int n = t; n < NTOK; n += 256) {
        #pragma unroll
        for (int e = 0; e < NE; e++) ps[e] += g_probs[n*NE + e];
    }
    __shared__ float red[NE + 1];
    sh[t] = ls; __syncthreads();
    for (int o = 128; o > 0; o >>= 1) { if (t < o) sh[t] += sh[t + o]; __syncthreads(); }
    if (t == 0) red[NE] = sh[0];
    __syncthreads();
    for (int e = 0; e < NE; e++) {
        sh[t] = ps[e]; __syncthreads();
        for (int o = 128; o > 0; o >>= 1) { if (t < o) sh[t] += sh[t + o]; __syncthreads(); }
        if (t == 0) red[e] = sh[0];
        __syncthreads();
    }
    if (t == 0) {
        float invN = 1.0f / (float)NTOK;
        float fb = 0.f;
        for (int e = 0; e < NE; e++) {
            float f_i = (float)g_counts[e] * invN;
            float p_i = red[e] * invN;
            fb += f_i * p_i;
        }
        float z = red[NE] * invN;
        out_aux[0] = 0.01f * (float)NE * fb + 0.001f * z;
    }
}

// ---------------------------------------------------------------------------
extern "C" void kernel_launch(void* const* d_in, const int* in_sizes, int n_in,
                              void* d_out, int out_size)
{
    const float* x  = (const float*)d_in[0];
    const float* Wg = (const float*)d_in[1];
    const float* W1 = (const float*)d_in[2];
    const float* b1 = (const float*)d_in[3];
    const float* W2 = (const float*)d_in[4];
    const float* b2 = (const float*)d_in[5];
    float* out = (float*)d_out;

    cudaFuncSetAttribute(tgemm_kernel<ND, NH, false>,
                         cudaFuncAttributeMaxDynamicSharedMemorySize, GSMEM);
    cudaFuncSetAttribute(tgemm_kernel<NH, ND, true>,
                         cudaFuncAttributeMaxDynamicSharedMemorySize, GSMEM);

    __half *xh, *hh, *w1h, *w2h;
    cudaGetSymbolAddress((void**)&xh,  g_xh);
    cudaGetSymbolAddress((void**)&hh,  g_hh);
    cudaGetSymbolAddress((void**)&w1h, g_w1h);
    cudaGetSymbolAddress((void**)&w2h, g_w2h);

    // launches 1-2: weight transpose + fp16 convert (independent of router)
    wconv_kernel<ND, NH><<<dim3(NH/32, ND/64, NE), dim3(32, 8)>>>(W1, w1h);
    wconv_kernel<NH, ND><<<dim3(ND/32, NH/64, NE), dim3(32, 8)>>>(W2, w2h);

    // launches 3-5: routing chain
    router_kernel<<<NTOK/8, 256>>>(x, Wg);
    rank_kernel<<<1, 1024>>>();
    gather_kernel<<<NTOK, 256>>>(x, out);

    // launch 6 (ncu -s 5 -c 1 profiles this): GEMM1
    tgemm_kernel<ND, NH, false><<<dim3(NH/128, MT/128), 128, GSMEM>>>(
        xh, w1h, b1, out);
    // launch 7: GEMM2 -> bias + scale -> scatter to out
    tgemm_kernel<NH, ND, true><<<dim3(ND/128, MT/128), 128, GSMEM>>>(
        hh, w2h, b2, out);

    if (out_size > NTOK * ND) {
        aux_kernel<<<1, 256>>>(out + (size_t)NTOK * ND);
    }
}